// round 4
// baseline (speedup 1.0000x reference)
#include <cuda_runtime.h>
#include <math.h>
#include <stdint.h>

#define B_  32
#define T_  127
#define S_  256
#define H_  512
#define V_  8000
#define NH_ 8
#define HD_ 64
#define G_  2048          // 4*H
#define M_BT (B_*T_)      // 4064
#define M_BS (B_*S_)      // 8192
#define SG_K 512

// ---------------- scratch (static device globals; no allocation) -------------
__device__ float g_emb [M_BT * H_];
__device__ float g_xg  [M_BT * G_];
__device__ float g_xgT [(size_t)T_ * G_ * B_];   // [t][gate_row][b]
__device__ float g_lstm[M_BT * H_];
__device__ float g_q   [M_BT * H_];
__device__ float g_k   [M_BS * H_];
__device__ float g_v   [M_BS * H_];
__device__ float g_ctx [M_BT * H_];
__device__ float g_comb[M_BT * H_];
__device__ float g_hbufT[3][H_ * B_];            // h state, [j][b] layout, triple buffered
__device__ unsigned int g_bar[128];              // per-block monotone barrier flags
__device__ unsigned g_tA[(size_t)M_BS * 512];    // tf32-converted activation operand
__device__ unsigned g_tW[(size_t)V_  * 512];     // tf32-converted weight operand

// ---------------- tf32 helpers -----------------------------------------------
__device__ __forceinline__ unsigned f2tf(float x) {
    unsigned u;
    asm("cvt.rna.tf32.f32 %0, %1;" : "=r"(u) : "f"(x));
    return u;
}

#define MMA_TF32(d0,d1,d2,d3,a0,a1,a2,a3,b0,b1)                             \
    asm volatile("mma.sync.aligned.m16n8k8.row.col.f32.tf32.tf32.f32 "      \
                 "{%0,%1,%2,%3},{%4,%5,%6,%7},{%8,%9},{%0,%1,%2,%3};"       \
                 : "+f"(d0), "+f"(d1), "+f"(d2), "+f"(d3)                   \
                 : "r"(a0), "r"(a1), "r"(a2), "r"(a3), "r"(b0), "r"(b1))

// ---------------- 0) fp32 -> tf32 conversion ---------------------------------
__global__ __launch_bounds__(256) void k_cvt(const float* __restrict__ in,
                                             unsigned* __restrict__ outp, int n4)
{
    int i = blockIdx.x * blockDim.x + threadIdx.x;
    if (i < n4) {
        float4 v = ((const float4*)in)[i];
        uint4 o;
        o.x = f2tf(v.x); o.y = f2tf(v.y); o.z = f2tf(v.z); o.w = f2tf(v.w);
        ((uint4*)outp)[i] = o;
    }
}

// ---------------- 1) embedding gather ---------------------------------------
__global__ void k_gather(const int* __restrict__ targets,
                         const float* __restrict__ emb)
{
    int m = blockIdx.x;            // m = b*T + t
    int b = m / T_, t = m % T_;
    int tok = targets[b * 128 + t];
    const float4* src = (const float4*)(emb + (size_t)tok * H_);
    float4*       dst = (float4*)(g_emb + (size_t)m * H_);
    for (int i = threadIdx.x; i < H_ / 4; i += blockDim.x) dst[i] = src[i];
}

// ---------------- 2) FFMA SGEMM (xg only; error isolation) -------------------
__global__ __launch_bounds__(256) void k_sgemm(
    const float* __restrict__ A, const float* __restrict__ W,
    const float* __restrict__ bias1, const float* __restrict__ bias2,
    float* __restrict__ C, int M, int N)
{
    __shared__ float As[16][132];
    __shared__ float Ws[16][132];
    int tid = threadIdx.x;
    int m0 = blockIdx.y * 128;
    int n0 = blockIdx.x * 128;
    int tx = tid & 15, ty = tid >> 4;
    int lrow = tid >> 1;           // 0..127
    int lk   = (tid & 1) * 8;      // 0 or 8

    float acc[8][8];
#pragma unroll
    for (int i = 0; i < 8; i++)
#pragma unroll
        for (int j = 0; j < 8; j++) acc[i][j] = 0.f;

    for (int k0 = 0; k0 < SG_K; k0 += 16) {
        {
            int gm = m0 + lrow; if (gm > M - 1) gm = M - 1;
            const float4* p = (const float4*)(A + (size_t)gm * SG_K + k0 + lk);
            float4 v0 = p[0], v1 = p[1];
            As[lk+0][lrow] = v0.x; As[lk+1][lrow] = v0.y;
            As[lk+2][lrow] = v0.z; As[lk+3][lrow] = v0.w;
            As[lk+4][lrow] = v1.x; As[lk+5][lrow] = v1.y;
            As[lk+6][lrow] = v1.z; As[lk+7][lrow] = v1.w;
            int gn = n0 + lrow; if (gn > N - 1) gn = N - 1;
            const float4* q = (const float4*)(W + (size_t)gn * SG_K + k0 + lk);
            float4 w0 = q[0], w1 = q[1];
            Ws[lk+0][lrow] = w0.x; Ws[lk+1][lrow] = w0.y;
            Ws[lk+2][lrow] = w0.z; Ws[lk+3][lrow] = w0.w;
            Ws[lk+4][lrow] = w1.x; Ws[lk+5][lrow] = w1.y;
            Ws[lk+6][lrow] = w1.z; Ws[lk+7][lrow] = w1.w;
        }
        __syncthreads();
#pragma unroll
        for (int k = 0; k < 16; k++) {
            float ra[8], rb[8];
#pragma unroll
            for (int i = 0; i < 8; i++) ra[i] = As[k][ty*8 + i];
#pragma unroll
            for (int j = 0; j < 8; j++) rb[j] = Ws[k][tx*8 + j];
#pragma unroll
            for (int i = 0; i < 8; i++)
#pragma unroll
                for (int j = 0; j < 8; j++) acc[i][j] += ra[i] * rb[j];
        }
        __syncthreads();
    }
#pragma unroll
    for (int i = 0; i < 8; i++) {
        int m = m0 + ty*8 + i;
        if (m >= M) continue;
#pragma unroll
        for (int j = 0; j < 8; j++) {
            int n = n0 + tx*8 + j;
            if (n >= N) continue;
            float v = acc[i][j];
            if (bias1)  v += bias1[n];
            if (bias2)  v += bias2[n];
            C[(size_t)m * N + n] = v;
        }
    }
}

// ---------------- 2b) pipelined tf32 tensor GEMM (preconverted operands) -----
// C[M,N] = A[M,512] @ W[N,512]^T (+bias)(+addsrc). 128x128 tile, BK=16,
// cp.async 2-stage double buffer, m-major smem with PAD=20 (conflict-free).
#define PAD 20

__global__ __launch_bounds__(256) void k_mm(
    const unsigned* __restrict__ A, const unsigned* __restrict__ W,
    const float* __restrict__ bias, const float* __restrict__ addsrc,
    float* __restrict__ C, int M, int N)
{
    __shared__ unsigned As[2][128 * PAD];
    __shared__ unsigned Ws[2][128 * PAD];
    int tid  = threadIdx.x;
    int lane = tid & 31, warp = tid >> 5;
    int warpM = warp & 3, warpN = warp >> 2;   // warp tile (32m, 64n)
    int m0 = blockIdx.y * 128;
    int n0 = blockIdx.x * 128;
    int lrow  = tid >> 1;          // 0..127
    int lpart = (tid & 1) * 8;     // k offset 0 or 8 (8 uints = 2 x 16B)

    int gm = m0 + lrow; if (gm > M - 1) gm = M - 1;
    int gn = n0 + lrow; if (gn > N - 1) gn = N - 1;
    const unsigned* Ap = A + (size_t)gm * SG_K + lpart;
    const unsigned* Wp = W + (size_t)gn * SG_K + lpart;
    unsigned sa_base = (unsigned)__cvta_generic_to_shared(&As[0][0]);
    unsigned sw_base = (unsigned)__cvta_generic_to_shared(&Ws[0][0]);
    unsigned soff = (unsigned)(lrow * PAD + lpart) * 4u;

    float acc[2][8][4];
#pragma unroll
    for (int i = 0; i < 2; i++)
#pragma unroll
        for (int j = 0; j < 8; j++)
#pragma unroll
            for (int r = 0; r < 4; r++) acc[i][j][r] = 0.f;

    int c = lane & 3, g = lane >> 2;

#define ISSUE(s, k0) do {                                                     \
        unsigned da = sa_base + (unsigned)(s) * 128u * PAD * 4u + soff;       \
        unsigned dw = sw_base + (unsigned)(s) * 128u * PAD * 4u + soff;       \
        const unsigned* pa = Ap + (k0);                                       \
        const unsigned* pw = Wp + (k0);                                       \
        asm volatile("cp.async.ca.shared.global [%0],[%1],16;\n\t"            \
                     "cp.async.ca.shared.global [%2],[%3],16;\n\t"            \
                     "cp.async.ca.shared.global [%4],[%5],16;\n\t"            \
                     "cp.async.ca.shared.global [%6],[%7],16;\n\t"            \
                     "cp.async.commit_group;\n\t"                             \
            :: "r"(da), "l"(pa), "r"(da + 16u), "l"(pa + 4),                  \
               "r"(dw), "l"(pw), "r"(dw + 16u), "l"(pw + 4));                 \
    } while (0)

    ISSUE(0, 0);
    for (int it = 0; it < 32; ++it) {
        if (it + 1 < 32) {
            ISSUE((it + 1) & 1, (it + 1) * 16);
            asm volatile("cp.async.wait_group 1;");
        } else {
            asm volatile("cp.async.wait_group 0;");
        }
        __syncthreads();
        const unsigned* as_ = &As[it & 1][0];
        const unsigned* ws_ = &Ws[it & 1][0];
#pragma unroll
        for (int kk = 0; kk < 16; kk += 8) {
            unsigned af[2][4];
#pragma unroll
            for (int mi = 0; mi < 2; mi++) {
                int mb = warpM * 32 + mi * 16;
                af[mi][0] = as_[(mb + g    ) * PAD + kk + c    ];
                af[mi][1] = as_[(mb + g + 8) * PAD + kk + c    ];
                af[mi][2] = as_[(mb + g    ) * PAD + kk + c + 4];
                af[mi][3] = as_[(mb + g + 8) * PAD + kk + c + 4];
            }
            unsigned bf[8][2];
#pragma unroll
            for (int ni = 0; ni < 8; ni++) {
                int nb = warpN * 64 + ni * 8;
                bf[ni][0] = ws_[(nb + g) * PAD + kk + c    ];
                bf[ni][1] = ws_[(nb + g) * PAD + kk + c + 4];
            }
#pragma unroll
            for (int mi = 0; mi < 2; mi++)
#pragma unroll
                for (int ni = 0; ni < 8; ni++)
                    MMA_TF32(acc[mi][ni][0], acc[mi][ni][1],
                             acc[mi][ni][2], acc[mi][ni][3],
                             af[mi][0], af[mi][1], af[mi][2], af[mi][3],
                             bf[ni][0], bf[ni][1]);
        }
        __syncthreads();
    }
#undef ISSUE
    // epilogue: c0:(g, 2q) c1:(g, 2q+1) c2:(g+8, 2q) c3:(g+8, 2q+1)
    int q = lane & 3;
#pragma unroll
    for (int mi = 0; mi < 2; mi++) {
        int m_lo = m0 + warpM * 32 + mi * 16 + g;
        int m_hi = m_lo + 8;
#pragma unroll
        for (int ni = 0; ni < 8; ni++) {
            int n = n0 + warpN * 64 + ni * 8 + 2 * q;
            if (n >= N) continue;     // N even, n even -> n+1 < N too
            float b0v = 0.f, b1v = 0.f;
            if (bias) { b0v = bias[n]; b1v = bias[n+1]; }
            if (m_lo < M) {
                float v0 = acc[mi][ni][0] + b0v;
                float v1 = acc[mi][ni][1] + b1v;
                if (addsrc) {
                    v0 += addsrc[(size_t)m_lo * N + n];
                    v1 += addsrc[(size_t)m_lo * N + n + 1];
                }
                *(float2*)(C + (size_t)m_lo * N + n) = make_float2(v0, v1);
            }
            if (m_hi < M) {
                float v2 = acc[mi][ni][2] + b0v;
                float v3 = acc[mi][ni][3] + b1v;
                if (addsrc) {
                    v2 += addsrc[(size_t)m_hi * N + n];
                    v3 += addsrc[(size_t)m_hi * N + n + 1];
                }
                *(float2*)(C + (size_t)m_hi * N + n) = make_float2(v2, v3);
            }
        }
    }
}

// ---------------- 3) transpose xg -> [t][gate_row][b] ------------------------
__global__ __launch_bounds__(256) void k_xgT()
{
    __shared__ float sm[32][33];
    int nc = blockIdx.x;           // 64 chunks of 32 gate-rows
    int t  = blockIdx.y;
    int lane = threadIdx.x & 31, w = threadIdx.x >> 5;
    for (int bb = w; bb < 32; bb += 8)
        sm[lane][bb] = g_xg[(size_t)(bb * T_ + t) * G_ + nc * 32 + lane];
    __syncthreads();
    for (int nn = w; nn < 32; nn += 8)
        g_xgT[((size_t)t * G_ + nc * 32 + nn) * 32 + lane] = sm[nn][lane];
}

// ---------------- 4) persistent LSTM (unchanged from R3) ---------------------
#define LNB 128
#define LTH 256
#define LSTM_SMEM ((16*512 + 512*32 + 16*32) * 4)

__global__ __launch_bounds__(LTH) void k_lstm(const float* __restrict__ whh)
{
    extern __shared__ float sm[];
    float* w_sm = sm;                 // [16][512]
    float* h_sm = sm + 16 * 512;      // [512][32]  h[k][b]
    float* g_sm = h_sm + 512 * 32;    // [16][32]
    int tid = threadIdx.x, bid = blockIdx.x;
    int lane = tid & 31, warp = tid >> 5;

    for (int idx = tid; idx < 16 * 512; idx += LTH) {
        int r = idx >> 9, k = idx & 511;
        int gate = r >> 2, u = r & 3;
        w_sm[idx] = whh[(size_t)(gate * H_ + bid * 4 + u) * H_ + k];
    }
    unsigned base = *((volatile unsigned*)&g_bar[bid]);
    float c_reg = 0.f;
    int uu = tid >> 5;
    __syncthreads();

    for (int t = 0; t < T_; t++) {
        if (t > 0) {
            unsigned target = base + (unsigned)t;
            for (;;) {
                int ok = 1;
                if (tid < LNB) {
                    unsigned v = *((volatile unsigned*)&g_bar[tid]);
                    ok = (v >= target) ? 1 : 0;
                }
                if (__syncthreads_and(ok)) break;
            }
            __threadfence();
            const float4* hb = (const float4*)g_hbufT[(t - 1) % 3];
            float4* hd = (float4*)h_sm;
            for (int i = tid; i < H_ * B_ / 4; i += LTH)
                hd[i] = __ldcg(hb + i);
            __syncthreads();
        }
        float a0 = 0.f, a1 = 0.f, a2 = 0.f, a3 = 0.f;
        if (t > 0 && warp < 4) {
            const float* w0 = &w_sm[(warp*4 + 0) * 512];
            const float* w1 = &w_sm[(warp*4 + 1) * 512];
            const float* w2 = &w_sm[(warp*4 + 2) * 512];
            const float* w3 = &w_sm[(warp*4 + 3) * 512];
#pragma unroll 4
            for (int k = 0; k < 512; k += 4) {
                float h0 = h_sm[(k+0)*32 + lane];
                float h1 = h_sm[(k+1)*32 + lane];
                float h2 = h_sm[(k+2)*32 + lane];
                float h3 = h_sm[(k+3)*32 + lane];
                float4 wa = *(const float4*)&w0[k];
                float4 wb = *(const float4*)&w1[k];
                float4 wc = *(const float4*)&w2[k];
                float4 wd = *(const float4*)&w3[k];
                a0 += h0*wa.x + h1*wa.y + h2*wa.z + h3*wa.w;
                a1 += h0*wb.x + h1*wb.y + h2*wb.z + h3*wb.w;
                a2 += h0*wc.x + h1*wc.y + h2*wc.z + h3*wc.w;
                a3 += h0*wd.x + h1*wd.y + h2*wd.z + h3*wd.w;
            }
        }
        if (warp < 4) {
            g_sm[(warp*4 + 0)*32 + lane] = a0;
            g_sm[(warp*4 + 1)*32 + lane] = a1;
            g_sm[(warp*4 + 2)*32 + lane] = a2;
            g_sm[(warp*4 + 3)*32 + lane] = a3;
        }
        __syncthreads();
        if (tid < 128) {
            int b = lane;
            int j = bid * 4 + uu;
            const float* xt = g_xgT + (size_t)t * G_ * B_;
            float gi = g_sm[(0*4+uu)*32 + b] + xt[((size_t)(0*H_ + j)) * B_ + b];
            float gf = g_sm[(1*4+uu)*32 + b] + xt[((size_t)(1*H_ + j)) * B_ + b];
            float gg = g_sm[(2*4+uu)*32 + b] + xt[((size_t)(2*H_ + j)) * B_ + b];
            float go = g_sm[(3*4+uu)*32 + b] + xt[((size_t)(3*H_ + j)) * B_ + b];
            float i_ = 1.f / (1.f + __expf(-gi));
            float f_ = 1.f / (1.f + __expf(-gf));
            float gv = tanhf(gg);
            float o_ = 1.f / (1.f + __expf(-go));
            c_reg = f_ * c_reg + i_ * gv;
            float h = o_ * tanhf(c_reg);
            g_hbufT[t % 3][j * B_ + b] = h;
            g_lstm[(size_t)(b * T_ + t) * H_ + j] = h;
            __threadfence();
        }
        __syncthreads();
        if (tid == 0)
            *((volatile unsigned*)&g_bar[bid]) = base + (unsigned)(t + 1);
    }
}

// ---------------- 5) attention (unchanged from R3) ---------------------------
__global__ __launch_bounds__(256) void k_attn()
{
    __shared__ float q_s[64];
    __shared__ float attn_s[256];
    __shared__ float red[8];
    __shared__ float ctxp[4][64];
    int tid = threadIdx.x;
    int nh = blockIdx.x, b = blockIdx.y;
    int lane = tid & 31, w = tid >> 5;
    const float* kb = g_k + (size_t)b * S_ * H_ + nh * HD_;
    const float* vb = g_v + (size_t)b * S_ * H_ + nh * HD_;

    for (int t = 0; t < T_; t++) {
        if (tid < 64)
            q_s[tid] = g_q[(size_t)(b * T_ + t) * H_ + nh * HD_ + tid];
        __syncthreads();
        const float* kr = kb + (size_t)tid * H_;
        float sc = 0.f;
#pragma unroll
        for (int d = 0; d < 64; d += 4) {
            float4 kk = *(const float4*)(kr + d);
            sc += q_s[d]*kk.x + q_s[d+1]*kk.y + q_s[d+2]*kk.z + q_s[d+3]*kk.w;
        }
        sc *= 0.125f;
        float mx = sc;
#pragma unroll
        for (int o = 16; o; o >>= 1) mx = fmaxf(mx, __shfl_xor_sync(0xffffffffu, mx, o));
        if (lane == 0) red[w] = mx;
        __syncthreads();
        mx = red[0];
#pragma unroll
        for (int i = 1; i < 8; i++) mx = fmaxf(mx, red[i]);
        float e = __expf(sc - mx);
        float sum = e;
#pragma unroll
        for (int o = 16; o; o >>= 1) sum += __shfl_xor_sync(0xffffffffu, sum, o);
        __syncthreads();
        if (lane == 0) red[w] = sum;
        __syncthreads();
        sum = red[0] + red[1] + red[2] + red[3] + red[4] + red[5] + red[6] + red[7];
        attn_s[tid] = e * (1.f / sum);
        __syncthreads();
        int d = tid & 63, scn = tid >> 6;
        const float* vr = vb + (size_t)(scn * 64) * H_ + d;
        float a = 0.f;
#pragma unroll 8
        for (int s = 0; s < 64; s++) a += attn_s[scn * 64 + s] * vr[(size_t)s * H_];
        ctxp[scn][d] = a;
        __syncthreads();
        if (tid < 64)
            g_ctx[(size_t)(b * T_ + t) * H_ + nh * HD_ + tid] =
                ctxp[0][tid] + ctxp[1][tid] + ctxp[2][tid] + ctxp[3][tid];
        __syncthreads();
    }
}

// ---------------- launcher ---------------------------------------------------
static inline void cvt(const float* src, unsigned* dst, size_t nelem)
{
    int n4 = (int)(nelem / 4);
    k_cvt<<<(n4 + 255) / 256, 256>>>(src, dst, n4);
}

extern "C" void kernel_launch(void* const* d_in, const int* in_sizes, int n_in,
                              void* d_out, int out_size)
{
    const int*   targets    = (const int*)  d_in[0];
    const float* enc        = (const float*)d_in[1];
    const float* embedding  = (const float*)d_in[2];
    const float* w_ih       = (const float*)d_in[3];
    const float* w_hh       = (const float*)d_in[4];
    const float* b_ih       = (const float*)d_in[5];
    const float* b_hh       = (const float*)d_in[6];
    const float* in_proj_w  = (const float*)d_in[7];
    const float* in_proj_b  = (const float*)d_in[8];
    const float* out_proj_w = (const float*)d_in[9];
    const float* out_proj_b = (const float*)d_in[10];
    const float* fc_w       = (const float*)d_in[11];
    const float* fc_b       = (const float*)d_in[12];
    float* out = (float*)d_out;

    float *p_emb, *p_xg, *p_lstm, *p_q, *p_k, *p_v, *p_ctx, *p_comb;
    unsigned *p_tA, *p_tW;
    cudaGetSymbolAddress((void**)&p_emb,  g_emb);
    cudaGetSymbolAddress((void**)&p_xg,   g_xg);
    cudaGetSymbolAddress((void**)&p_lstm, g_lstm);
    cudaGetSymbolAddress((void**)&p_q,    g_q);
    cudaGetSymbolAddress((void**)&p_k,    g_k);
    cudaGetSymbolAddress((void**)&p_v,    g_v);
    cudaGetSymbolAddress((void**)&p_ctx,  g_ctx);
    cudaGetSymbolAddress((void**)&p_comb, g_comb);
    cudaGetSymbolAddress((void**)&p_tA,   g_tA);
    cudaGetSymbolAddress((void**)&p_tW,   g_tW);

    cudaFuncSetAttribute(k_lstm, cudaFuncAttributeMaxDynamicSharedMemorySize,
                         LSTM_SMEM);

    // 1) embedding gather
    k_gather<<<M_BT, 128>>>(targets, embedding);
    // 2) xg = emb @ w_ih^T + b_ih + b_hh   (fp32 FFMA: keeps recurrence exact)
    k_sgemm<<<dim3(G_/128, (M_BT+127)/128), 256>>>(p_emb, w_ih, b_ih, b_hh,
                                                   p_xg, M_BT, G_);
    // 3) transpose xg to [t][gate_row][b]
    k_xgT<<<dim3(64, T_), 256>>>();
    // 4) persistent LSTM over 127 steps
    k_lstm<<<LNB, LTH, LSTM_SMEM>>>(w_hh);
    // 5) q projection
    cvt(p_lstm, p_tA, (size_t)M_BT * 512);
    cvt(in_proj_w, p_tW, (size_t)H_ * 512);
    k_mm<<<dim3(4, (M_BT+127)/128), 256>>>(p_tA, p_tW, in_proj_b,
                                           nullptr, p_q, M_BT, H_);
    // 6) k/v projections of encoder outputs
    cvt(enc, p_tA, (size_t)M_BS * 512);
    cvt(in_proj_w + (size_t)H_*H_, p_tW, (size_t)H_ * 512);
    k_mm<<<dim3(4, M_BS/128), 256>>>(p_tA, p_tW, in_proj_b + H_,
                                     nullptr, p_k, M_BS, H_);
    cvt(in_proj_w + (size_t)2*H_*H_, p_tW, (size_t)H_ * 512);
    k_mm<<<dim3(4, M_BS/128), 256>>>(p_tA, p_tW, in_proj_b + 2*H_,
                                     nullptr, p_v, M_BS, H_);
    // 7) attention
    k_attn<<<dim3(NH_, B_), 256>>>();
    // 8) combined = ctx @ out_proj^T + b + lstm_out (fused residual)
    cvt(p_ctx, p_tA, (size_t)M_BT * 512);
    cvt(out_proj_w, p_tW, (size_t)H_ * 512);
    k_mm<<<dim3(4, (M_BT+127)/128), 256>>>(p_tA, p_tW, out_proj_b,
                                           p_lstm, p_comb, M_BT, H_);
    // 9) logits = combined @ fc_w^T + fc_b
    cvt(p_comb, p_tA, (size_t)M_BT * 512);
    cvt(fc_w, p_tW, (size_t)V_ * 512);
    k_mm<<<dim3((V_+127)/128, (M_BT+127)/128), 256>>>(p_tA, p_tW, fc_b,
                                                      nullptr, out, M_BT, V_);
}

// round 6
// speedup vs baseline: 1.1580x; 1.1580x over previous
#include <cuda_runtime.h>
#include <math.h>
#include <stdint.h>

#define B_  32
#define T_  127
#define S_  256
#define H_  512
#define V_  8000
#define NH_ 8
#define HD_ 64
#define G_  2048          // 4*H
#define M_BT (B_*T_)      // 4064
#define M_BS (B_*S_)      // 8192
#define SG_K 512

// ---------------- scratch (static device globals; no allocation) -------------
__device__ float g_emb [M_BT * H_];
__device__ float g_xg  [M_BT * G_];
__device__ float g_xgT [(size_t)T_ * G_ * B_];   // [t][gate_row][b]
__device__ float g_lstm[M_BT * H_];
__device__ float g_q   [M_BT * H_];
__device__ float g_k   [M_BS * H_];
__device__ float g_v   [M_BS * H_];
__device__ float g_ctx [M_BT * H_];
__device__ float g_comb[M_BT * H_];
__device__ float g_hbufT[3][H_ * B_];            // h state, [j][b] layout, triple buffered
__device__ unsigned int g_bar[128];              // per-block monotone barrier flags
__device__ unsigned g_tA[(size_t)M_BS * 512];    // tf32-converted activation operand
__device__ unsigned g_tW[(size_t)V_  * 512];     // tf32-converted weight operand

// ---------------- tf32 helpers -----------------------------------------------
__device__ __forceinline__ unsigned f2tf(float x) {
    unsigned u;
    asm("cvt.rna.tf32.f32 %0, %1;" : "=r"(u) : "f"(x));
    return u;
}

#define MMA_TF32(d0,d1,d2,d3,a0,a1,a2,a3,b0,b1)                             \
    asm volatile("mma.sync.aligned.m16n8k8.row.col.f32.tf32.tf32.f32 "      \
                 "{%0,%1,%2,%3},{%4,%5,%6,%7},{%8,%9},{%0,%1,%2,%3};"       \
                 : "+f"(d0), "+f"(d1), "+f"(d2), "+f"(d3)                   \
                 : "r"(a0), "r"(a1), "r"(a2), "r"(a3), "r"(b0), "r"(b1))

// ---------------- 0) fp32 -> tf32 conversion ---------------------------------
__global__ __launch_bounds__(256) void k_cvt(const float* __restrict__ in,
                                             unsigned* __restrict__ outp, int n4)
{
    int i = blockIdx.x * blockDim.x + threadIdx.x;
    if (i < n4) {
        float4 v = ((const float4*)in)[i];
        uint4 o;
        o.x = f2tf(v.x); o.y = f2tf(v.y); o.z = f2tf(v.z); o.w = f2tf(v.w);
        ((uint4*)outp)[i] = o;
    }
}

// ---------------- 1) embedding gather ---------------------------------------
__global__ void k_gather(const int* __restrict__ targets,
                         const float* __restrict__ emb)
{
    int m = blockIdx.x;            // m = b*T + t
    int b = m / T_, t = m % T_;
    int tok = targets[b * 128 + t];
    const float4* src = (const float4*)(emb + (size_t)tok * H_);
    float4*       dst = (float4*)(g_emb + (size_t)m * H_);
    for (int i = threadIdx.x; i < H_ / 4; i += blockDim.x) dst[i] = src[i];
}

// ---------------- 2) FFMA SGEMM (xg only; error isolation) -------------------
__global__ __launch_bounds__(256) void k_sgemm(
    const float* __restrict__ A, const float* __restrict__ W,
    const float* __restrict__ bias1, const float* __restrict__ bias2,
    float* __restrict__ C, int M, int N)
{
    __shared__ float As[16][132];
    __shared__ float Ws[16][132];
    int tid = threadIdx.x;
    int m0 = blockIdx.y * 128;
    int n0 = blockIdx.x * 128;
    int tx = tid & 15, ty = tid >> 4;
    int lrow = tid >> 1;           // 0..127
    int lk   = (tid & 1) * 8;      // 0 or 8

    float acc[8][8];
#pragma unroll
    for (int i = 0; i < 8; i++)
#pragma unroll
        for (int j = 0; j < 8; j++) acc[i][j] = 0.f;

    for (int k0 = 0; k0 < SG_K; k0 += 16) {
        {
            int gm = m0 + lrow; if (gm > M - 1) gm = M - 1;
            const float4* p = (const float4*)(A + (size_t)gm * SG_K + k0 + lk);
            float4 v0 = p[0], v1 = p[1];
            As[lk+0][lrow] = v0.x; As[lk+1][lrow] = v0.y;
            As[lk+2][lrow] = v0.z; As[lk+3][lrow] = v0.w;
            As[lk+4][lrow] = v1.x; As[lk+5][lrow] = v1.y;
            As[lk+6][lrow] = v1.z; As[lk+7][lrow] = v1.w;
            int gn = n0 + lrow; if (gn > N - 1) gn = N - 1;
            const float4* q = (const float4*)(W + (size_t)gn * SG_K + k0 + lk);
            float4 w0 = q[0], w1 = q[1];
            Ws[lk+0][lrow] = w0.x; Ws[lk+1][lrow] = w0.y;
            Ws[lk+2][lrow] = w0.z; Ws[lk+3][lrow] = w0.w;
            Ws[lk+4][lrow] = w1.x; Ws[lk+5][lrow] = w1.y;
            Ws[lk+6][lrow] = w1.z; Ws[lk+7][lrow] = w1.w;
        }
        __syncthreads();
#pragma unroll
        for (int k = 0; k < 16; k++) {
            float ra[8], rb[8];
#pragma unroll
            for (int i = 0; i < 8; i++) ra[i] = As[k][ty*8 + i];
#pragma unroll
            for (int j = 0; j < 8; j++) rb[j] = Ws[k][tx*8 + j];
#pragma unroll
            for (int i = 0; i < 8; i++)
#pragma unroll
                for (int j = 0; j < 8; j++) acc[i][j] += ra[i] * rb[j];
        }
        __syncthreads();
    }
#pragma unroll
    for (int i = 0; i < 8; i++) {
        int m = m0 + ty*8 + i;
        if (m >= M) continue;
#pragma unroll
        for (int j = 0; j < 8; j++) {
            int n = n0 + tx*8 + j;
            if (n >= N) continue;
            float v = acc[i][j];
            if (bias1)  v += bias1[n];
            if (bias2)  v += bias2[n];
            C[(size_t)m * N + n] = v;
        }
    }
}

// ---------------- 2b) pipelined tf32 tensor GEMM (preconverted operands) -----
#define PAD 20

__global__ __launch_bounds__(256) void k_mm(
    const unsigned* __restrict__ A, const unsigned* __restrict__ W,
    const float* __restrict__ bias, const float* __restrict__ addsrc,
    float* __restrict__ C, int M, int N)
{
    __shared__ unsigned As[2][128 * PAD];
    __shared__ unsigned Ws[2][128 * PAD];
    int tid  = threadIdx.x;
    int lane = tid & 31, warp = tid >> 5;
    int warpM = warp & 3, warpN = warp >> 2;   // warp tile (32m, 64n)
    int m0 = blockIdx.y * 128;
    int n0 = blockIdx.x * 128;
    int lrow  = tid >> 1;          // 0..127
    int lpart = (tid & 1) * 8;     // k offset 0 or 8

    int gm = m0 + lrow; if (gm > M - 1) gm = M - 1;
    int gn = n0 + lrow; if (gn > N - 1) gn = N - 1;
    const unsigned* Ap = A + (size_t)gm * SG_K + lpart;
    const unsigned* Wp = W + (size_t)gn * SG_K + lpart;
    unsigned sa_base = (unsigned)__cvta_generic_to_shared(&As[0][0]);
    unsigned sw_base = (unsigned)__cvta_generic_to_shared(&Ws[0][0]);
    unsigned soff = (unsigned)(lrow * PAD + lpart) * 4u;

    float acc[2][8][4];
#pragma unroll
    for (int i = 0; i < 2; i++)
#pragma unroll
        for (int j = 0; j < 8; j++)
#pragma unroll
            for (int r = 0; r < 4; r++) acc[i][j][r] = 0.f;

    int c = lane & 3, g = lane >> 2;

#define ISSUE(s, k0) do {                                                     \
        unsigned da = sa_base + (unsigned)(s) * 128u * PAD * 4u + soff;       \
        unsigned dw = sw_base + (unsigned)(s) * 128u * PAD * 4u + soff;       \
        const unsigned* pa = Ap + (k0);                                       \
        const unsigned* pw = Wp + (k0);                                       \
        asm volatile("cp.async.ca.shared.global [%0],[%1],16;\n\t"            \
                     "cp.async.ca.shared.global [%2],[%3],16;\n\t"            \
                     "cp.async.ca.shared.global [%4],[%5],16;\n\t"            \
                     "cp.async.ca.shared.global [%6],[%7],16;\n\t"            \
                     "cp.async.commit_group;\n\t"                             \
            :: "r"(da), "l"(pa), "r"(da + 16u), "l"(pa + 4),                  \
               "r"(dw), "l"(pw), "r"(dw + 16u), "l"(pw + 4));                 \
    } while (0)

    ISSUE(0, 0);
    for (int it = 0; it < 32; ++it) {
        if (it + 1 < 32) {
            ISSUE((it + 1) & 1, (it + 1) * 16);
            asm volatile("cp.async.wait_group 1;");
        } else {
            asm volatile("cp.async.wait_group 0;");
        }
        __syncthreads();
        const unsigned* as_ = &As[it & 1][0];
        const unsigned* ws_ = &Ws[it & 1][0];
#pragma unroll
        for (int kk = 0; kk < 16; kk += 8) {
            unsigned af[2][4];
#pragma unroll
            for (int mi = 0; mi < 2; mi++) {
                int mb = warpM * 32 + mi * 16;
                af[mi][0] = as_[(mb + g    ) * PAD + kk + c    ];
                af[mi][1] = as_[(mb + g + 8) * PAD + kk + c    ];
                af[mi][2] = as_[(mb + g    ) * PAD + kk + c + 4];
                af[mi][3] = as_[(mb + g + 8) * PAD + kk + c + 4];
            }
            unsigned bf[8][2];
#pragma unroll
            for (int ni = 0; ni < 8; ni++) {
                int nb = warpN * 64 + ni * 8;
                bf[ni][0] = ws_[(nb + g) * PAD + kk + c    ];
                bf[ni][1] = ws_[(nb + g) * PAD + kk + c + 4];
            }
#pragma unroll
            for (int mi = 0; mi < 2; mi++)
#pragma unroll
                for (int ni = 0; ni < 8; ni++)
                    MMA_TF32(acc[mi][ni][0], acc[mi][ni][1],
                             acc[mi][ni][2], acc[mi][ni][3],
                             af[mi][0], af[mi][1], af[mi][2], af[mi][3],
                             bf[ni][0], bf[ni][1]);
        }
        __syncthreads();
    }
#undef ISSUE
    int q = lane & 3;
#pragma unroll
    for (int mi = 0; mi < 2; mi++) {
        int m_lo = m0 + warpM * 32 + mi * 16 + g;
        int m_hi = m_lo + 8;
#pragma unroll
        for (int ni = 0; ni < 8; ni++) {
            int n = n0 + warpN * 64 + ni * 8 + 2 * q;
            if (n >= N) continue;
            float b0v = 0.f, b1v = 0.f;
            if (bias) { b0v = bias[n]; b1v = bias[n+1]; }
            if (m_lo < M) {
                float v0 = acc[mi][ni][0] + b0v;
                float v1 = acc[mi][ni][1] + b1v;
                if (addsrc) {
                    v0 += addsrc[(size_t)m_lo * N + n];
                    v1 += addsrc[(size_t)m_lo * N + n + 1];
                }
                *(float2*)(C + (size_t)m_lo * N + n) = make_float2(v0, v1);
            }
            if (m_hi < M) {
                float v2 = acc[mi][ni][2] + b0v;
                float v3 = acc[mi][ni][3] + b1v;
                if (addsrc) {
                    v2 += addsrc[(size_t)m_hi * N + n];
                    v3 += addsrc[(size_t)m_hi * N + n + 1];
                }
                *(float2*)(C + (size_t)m_hi * N + n) = make_float2(v2, v3);
            }
        }
    }
}

// ---------------- 3) transpose xg -> [t][gate_row][b] ------------------------
__global__ __launch_bounds__(256) void k_xgT()
{
    __shared__ float sm[32][33];
    int nc = blockIdx.x;
    int t  = blockIdx.y;
    int lane = threadIdx.x & 31, w = threadIdx.x >> 5;
    for (int bb = w; bb < 32; bb += 8)
        sm[lane][bb] = g_xg[(size_t)(bb * T_ + t) * G_ + nc * 32 + lane];
    __syncthreads();
    for (int nn = w; nn < 32; nn += 8)
        g_xgT[((size_t)t * G_ + nc * 32 + nn) * 32 + lane] = sm[nn][lane];
}

// ---------------- 4) persistent LSTM (R4-proven barrier protocol) ------------
#define LNB 128
#define LTH 256
#define LSTM_SMEM ((16*512 + 512*32 + 16*32) * 4)

__global__ __launch_bounds__(LTH) void k_lstm(const float* __restrict__ whh)
{
    extern __shared__ float sm[];
    float* w_sm = sm;                 // [16][512]
    float* h_sm = sm + 16 * 512;      // [512][32]  h[k][b]
    float* g_sm = h_sm + 512 * 32;    // [16][32]
    int tid = threadIdx.x, bid = blockIdx.x;
    int lane = tid & 31, warp = tid >> 5;

    for (int idx = tid; idx < 16 * 512; idx += LTH) {
        int r = idx >> 9, k = idx & 511;
        int gate = r >> 2, u = r & 3;
        w_sm[idx] = whh[(size_t)(gate * H_ + bid * 4 + u) * H_ + k];
    }
    unsigned base = *((volatile unsigned*)&g_bar[bid]);
    float c_reg = 0.f;
    int uu = tid >> 5;
    __syncthreads();

    for (int t = 0; t < T_; t++) {
        if (t > 0) {
            unsigned target = base + (unsigned)t;
            for (;;) {
                int ok = 1;
                if (tid < LNB) {
                    unsigned v = *((volatile unsigned*)&g_bar[tid]);
                    ok = (v >= target) ? 1 : 0;
                }
                if (__syncthreads_and(ok)) break;
            }
            __threadfence();
            const float4* hb = (const float4*)g_hbufT[(t - 1) % 3];
            float4* hd = (float4*)h_sm;
            for (int i = tid; i < H_ * B_ / 4; i += LTH)
                hd[i] = __ldcg(hb + i);
            __syncthreads();
        }
        float a0 = 0.f, a1 = 0.f, a2 = 0.f, a3 = 0.f;
        if (t > 0 && warp < 4) {
            const float* w0 = &w_sm[(warp*4 + 0) * 512];
            const float* w1 = &w_sm[(warp*4 + 1) * 512];
            const float* w2 = &w_sm[(warp*4 + 2) * 512];
            const float* w3 = &w_sm[(warp*4 + 3) * 512];
#pragma unroll 4
            for (int k = 0; k < 512; k += 4) {
                float h0 = h_sm[(k+0)*32 + lane];
                float h1 = h_sm[(k+1)*32 + lane];
                float h2 = h_sm[(k+2)*32 + lane];
                float h3 = h_sm[(k+3)*32 + lane];
                float4 wa = *(const float4*)&w0[k];
                float4 wb = *(const float4*)&w1[k];
                float4 wc = *(const float4*)&w2[k];
                float4 wd = *(const float4*)&w3[k];
                a0 += h0*wa.x + h1*wa.y + h2*wa.z + h3*wa.w;
                a1 += h0*wb.x + h1*wb.y + h2*wb.z + h3*wb.w;
                a2 += h0*wc.x + h1*wc.y + h2*wc.z + h3*wc.w;
                a3 += h0*wd.x + h1*wd.y + h2*wd.z + h3*wd.w;
            }
        }
        if (warp < 4) {
            g_sm[(warp*4 + 0)*32 + lane] = a0;
            g_sm[(warp*4 + 1)*32 + lane] = a1;
            g_sm[(warp*4 + 2)*32 + lane] = a2;
            g_sm[(warp*4 + 3)*32 + lane] = a3;
        }
        __syncthreads();
        if (tid < 128) {
            int b = lane;
            int j = bid * 4 + uu;
            const float* xt = g_xgT + (size_t)t * G_ * B_;
            float gi = g_sm[(0*4+uu)*32 + b] + xt[((size_t)(0*H_ + j)) * B_ + b];
            float gf = g_sm[(1*4+uu)*32 + b] + xt[((size_t)(1*H_ + j)) * B_ + b];
            float gg = g_sm[(2*4+uu)*32 + b] + xt[((size_t)(2*H_ + j)) * B_ + b];
            float go = g_sm[(3*4+uu)*32 + b] + xt[((size_t)(3*H_ + j)) * B_ + b];
            float i_ = 1.f / (1.f + __expf(-gi));
            float f_ = 1.f / (1.f + __expf(-gf));
            float gv = tanhf(gg);
            float o_ = 1.f / (1.f + __expf(-go));
            c_reg = f_ * c_reg + i_ * gv;
            float h = o_ * tanhf(c_reg);
            g_hbufT[t % 3][j * B_ + b] = h;
            g_lstm[(size_t)(b * T_ + t) * H_ + j] = h;
            __threadfence();
        }
        __syncthreads();
        if (tid == 0)
            *((volatile unsigned*)&g_bar[bid]) = base + (unsigned)(t + 1);
    }
}

// ---------------- 5) attention: K^T + V staged in smem -----------------------
// One block per (head, batch). K^T [64][264], V [256][68] loaded once; the
// 127-query loop runs entirely from conflict-free smem.
#define KT_LD 264
#define VS_LD 68
#define ATT_SMEM ((64*KT_LD + 256*VS_LD + 64 + 256 + 8 + 256) * 4)

__global__ __launch_bounds__(256) void k_attn()
{
    extern __shared__ float smem[];
    float* KT     = smem;                       // [64][264]  KT[d][s]
    float* Vs     = KT + 64 * KT_LD;            // [256][68]  Vs[s][d]
    float* q_s    = Vs + 256 * VS_LD;           // [64]
    float* attn_s = q_s + 64;                   // [256]
    float* red    = attn_s + 256;               // [8]
    float* ctxp   = red + 8;                    // [4][64]
    int tid = threadIdx.x;
    int nh = blockIdx.x, b = blockIdx.y;
    int lane = tid & 31, w = tid >> 5;
    const float* kb = g_k + (size_t)b * S_ * H_ + nh * HD_;
    const float* vb = g_v + (size_t)b * S_ * H_ + nh * HD_;

    // one-time stage: 16384 floats each, float4 global reads
    for (int it = 0; it < 16; ++it) {
        int idx4 = it * 256 + tid;          // 0..4095
        int s = idx4 >> 4;                  // 0..255
        int d4 = (idx4 & 15) * 4;           // 0..60
        float4 kv = *(const float4*)(kb + (size_t)s * H_ + d4);
        float4 vv = *(const float4*)(vb + (size_t)s * H_ + d4);
        KT[(d4+0)*KT_LD + s] = kv.x;
        KT[(d4+1)*KT_LD + s] = kv.y;
        KT[(d4+2)*KT_LD + s] = kv.z;
        KT[(d4+3)*KT_LD + s] = kv.w;
        *(float4*)(Vs + s * VS_LD + d4) = vv;
    }
    __syncthreads();

    for (int t = 0; t < T_; t++) {
        if (tid < 64)
            q_s[tid] = g_q[(size_t)(b * T_ + t) * H_ + nh * HD_ + tid];
        __syncthreads();
        // scores: thread = key position s, reads KT[d][s] (lane-consecutive)
        float sc = 0.f;
#pragma unroll 16
        for (int d = 0; d < 64; d += 4) {
            sc += q_s[d+0] * KT[(d+0)*KT_LD + tid];
            sc += q_s[d+1] * KT[(d+1)*KT_LD + tid];
            sc += q_s[d+2] * KT[(d+2)*KT_LD + tid];
            sc += q_s[d+3] * KT[(d+3)*KT_LD + tid];
        }
        sc *= 0.125f;
        float mx = sc;
#pragma unroll
        for (int o = 16; o; o >>= 1) mx = fmaxf(mx, __shfl_xor_sync(0xffffffffu, mx, o));
        if (lane == 0) red[w] = mx;
        __syncthreads();
        mx = red[0];
#pragma unroll
        for (int i = 1; i < 8; i++) mx = fmaxf(mx, red[i]);
        float e = __expf(sc - mx);
        float sum = e;
#pragma unroll
        for (int o = 16; o; o >>= 1) sum += __shfl_xor_sync(0xffffffffu, sum, o);
        __syncthreads();
        if (lane == 0) red[w] = sum;
        __syncthreads();
        sum = red[0] + red[1] + red[2] + red[3] + red[4] + red[5] + red[6] + red[7];
        attn_s[tid] = e * (1.f / sum);
        __syncthreads();
        // ctx: 4 s-chunks x 64 dims, Vs reads lane-consecutive over d
        int d = tid & 63, scn = tid >> 6;
        float a = 0.f;
#pragma unroll 16
        for (int s = 0; s < 64; s++)
            a += attn_s[scn * 64 + s] * Vs[(scn * 64 + s) * VS_LD + d];
        ctxp[scn * 64 + d] = a;
        __syncthreads();
        if (tid < 64)
            g_ctx[(size_t)(b * T_ + t) * H_ + nh * HD_ + tid] =
                ctxp[0*64 + tid] + ctxp[1*64 + tid] +
                ctxp[2*64 + tid] + ctxp[3*64 + tid];
        __syncthreads();
    }
}

// ---------------- launcher ---------------------------------------------------
static inline void cvt(const float* src, unsigned* dst, size_t nelem)
{
    int n4 = (int)(nelem / 4);
    k_cvt<<<(n4 + 255) / 256, 256>>>(src, dst, n4);
}

extern "C" void kernel_launch(void* const* d_in, const int* in_sizes, int n_in,
                              void* d_out, int out_size)
{
    const int*   targets    = (const int*)  d_in[0];
    const float* enc        = (const float*)d_in[1];
    const float* embedding  = (const float*)d_in[2];
    const float* w_ih       = (const float*)d_in[3];
    const float* w_hh       = (const float*)d_in[4];
    const float* b_ih       = (const float*)d_in[5];
    const float* b_hh       = (const float*)d_in[6];
    const float* in_proj_w  = (const float*)d_in[7];
    const float* in_proj_b  = (const float*)d_in[8];
    const float* out_proj_w = (const float*)d_in[9];
    const float* out_proj_b = (const float*)d_in[10];
    const float* fc_w       = (const float*)d_in[11];
    const float* fc_b       = (const float*)d_in[12];
    float* out = (float*)d_out;

    float *p_emb, *p_xg, *p_lstm, *p_q, *p_k, *p_v, *p_ctx, *p_comb;
    unsigned *p_tA, *p_tW;
    cudaGetSymbolAddress((void**)&p_emb,  g_emb);
    cudaGetSymbolAddress((void**)&p_xg,   g_xg);
    cudaGetSymbolAddress((void**)&p_lstm, g_lstm);
    cudaGetSymbolAddress((void**)&p_q,    g_q);
    cudaGetSymbolAddress((void**)&p_k,    g_k);
    cudaGetSymbolAddress((void**)&p_v,    g_v);
    cudaGetSymbolAddress((void**)&p_ctx,  g_ctx);
    cudaGetSymbolAddress((void**)&p_comb, g_comb);
    cudaGetSymbolAddress((void**)&p_tA,   g_tA);
    cudaGetSymbolAddress((void**)&p_tW,   g_tW);

    cudaFuncSetAttribute(k_lstm, cudaFuncAttributeMaxDynamicSharedMemorySize,
                         LSTM_SMEM);
    cudaFuncSetAttribute(k_attn, cudaFuncAttributeMaxDynamicSharedMemorySize,
                         ATT_SMEM);

    // 1) embedding gather
    k_gather<<<M_BT, 128>>>(targets, embedding);
    // 2) xg = emb @ w_ih^T + b_ih + b_hh   (fp32 FFMA: keeps recurrence exact)
    k_sgemm<<<dim3(G_/128, (M_BT+127)/128), 256>>>(p_emb, w_ih, b_ih, b_hh,
                                                   p_xg, M_BT, G_);
    // 3) transpose xg to [t][gate_row][b]
    k_xgT<<<dim3(64, T_), 256>>>();
    // 4) persistent LSTM over 127 steps
    k_lstm<<<LNB, LTH, LSTM_SMEM>>>(w_hh);
    // 5) q projection
    cvt(p_lstm, p_tA, (size_t)M_BT * 512);
    cvt(in_proj_w, p_tW, (size_t)H_ * 512);
    k_mm<<<dim3(4, (M_BT+127)/128), 256>>>(p_tA, p_tW, in_proj_b,
                                           nullptr, p_q, M_BT, H_);
    // 6) k/v projections of encoder outputs
    cvt(enc, p_tA, (size_t)M_BS * 512);
    cvt(in_proj_w + (size_t)H_*H_, p_tW, (size_t)H_ * 512);
    k_mm<<<dim3(4, M_BS/128), 256>>>(p_tA, p_tW, in_proj_b + H_,
                                     nullptr, p_k, M_BS, H_);
    cvt(in_proj_w + (size_t)2*H_*H_, p_tW, (size_t)H_ * 512);
    k_mm<<<dim3(4, M_BS/128), 256>>>(p_tA, p_tW, in_proj_b + 2*H_,
                                     nullptr, p_v, M_BS, H_);
    // 7) attention (smem-resident K/V)
    k_attn<<<dim3(NH_, B_), 256, ATT_SMEM>>>();
    // 8) combined = ctx @ out_proj^T + b + lstm_out (fused residual)
    cvt(p_ctx, p_tA, (size_t)M_BT * 512);
    cvt(out_proj_w, p_tW, (size_t)H_ * 512);
    k_mm<<<dim3(4, (M_BT+127)/128), 256>>>(p_tA, p_tW, out_proj_b,
                                           p_lstm, p_comb, M_BT, H_);
    // 9) logits = combined @ fc_w^T + fc_b
    cvt(p_comb, p_tA, (size_t)M_BT * 512);
    cvt(fc_w, p_tW, (size_t)V_ * 512);
    k_mm<<<dim3((V_+127)/128, (M_BT+127)/128), 256>>>(p_tA, p_tW, fc_b,
                                                      nullptr, out, M_BT, V_);
}

// round 9
// speedup vs baseline: 1.2638x; 1.0913x over previous
#include <cuda_runtime.h>
#include <cuda_fp16.h>
#include <math.h>
#include <stdint.h>

#define B_  32
#define T_  127
#define S_  256
#define H_  512
#define V_  8000
#define NH_ 8
#define HD_ 64
#define G_  2048          // 4*H
#define M_BT (B_*T_)      // 4064
#define M_BS (B_*S_)      // 8192
#define SG_K 512
#define KW   256          // K in half2 words

// ---------------- scratch (static device globals; no allocation) -------------
__device__ float g_emb [M_BT * H_];
__device__ float g_xg  [M_BT * G_];
__device__ float g_xgT [(size_t)T_ * G_ * B_];   // [t][gate_row][b]
__device__ float g_lstm[M_BT * H_];
__device__ float g_q   [M_BT * H_];
__device__ float g_k   [M_BS * H_];
__device__ float g_v   [M_BS * H_];
__device__ float g_ctx [M_BT * H_];
__device__ float g_comb[M_BT * H_];
__device__ float g_hbufT[3][H_ * B_];            // h state, [j][b] layout
__device__ unsigned int g_bar[128];              // per-block monotone barrier flags
__device__ unsigned g_tA  [(size_t)M_BT * KW];   // fp16x2 activations
__device__ unsigned g_tEnc[(size_t)M_BS * KW];   // fp16x2 encoder outputs
__device__ unsigned g_tWq [(size_t)H_ * KW];
__device__ unsigned g_tWk [(size_t)H_ * KW];
__device__ unsigned g_tWv [(size_t)H_ * KW];
__device__ unsigned g_tWo [(size_t)H_ * KW];
__device__ unsigned g_tW  [(size_t)V_ * KW];     // fp16x2 fc weights

// ---------------- fp16 mma helper --------------------------------------------
#define MMA_F16(d0,d1,d2,d3,a0,a1,a2,a3,b0,b1)                              \
    asm volatile("mma.sync.aligned.m16n8k16.row.col.f32.f16.f16.f32 "       \
                 "{%0,%1,%2,%3},{%4,%5,%6,%7},{%8,%9},{%0,%1,%2,%3};"       \
                 : "+f"(d0), "+f"(d1), "+f"(d2), "+f"(d3)                   \
                 : "r"(a0), "r"(a1), "r"(a2), "r"(a3), "r"(b0), "r"(b1))

// ---------------- 0) fp32 -> fp16x2 conversion -------------------------------
__global__ __launch_bounds__(256) void k_cvth(const float* __restrict__ in,
                                              unsigned* __restrict__ outp, int n4)
{
    int i = blockIdx.x * blockDim.x + threadIdx.x;
    if (i < n4) {
        float4 v = ((const float4*)in)[i];
        __half2 h0 = __floats2half2_rn(v.x, v.y);
        __half2 h1 = __floats2half2_rn(v.z, v.w);
        uint2 o;
        o.x = *(unsigned*)&h0;
        o.y = *(unsigned*)&h1;
        ((uint2*)outp)[i] = o;
    }
}

// ---------------- 1) embedding gather ---------------------------------------
__global__ void k_gather(const int* __restrict__ targets,
                         const float* __restrict__ emb)
{
    int m = blockIdx.x;
    int b = m / T_, t = m % T_;
    int tok = targets[b * 128 + t];
    const float4* src = (const float4*)(emb + (size_t)tok * H_);
    float4*       dst = (float4*)(g_emb + (size_t)m * H_);
    for (int i = threadIdx.x; i < H_ / 4; i += blockDim.x) dst[i] = src[i];
}

// ---------------- 2) FFMA SGEMM (xg only; error isolation) -------------------
__global__ __launch_bounds__(256) void k_sgemm(
    const float* __restrict__ A, const float* __restrict__ W,
    const float* __restrict__ bias1, const float* __restrict__ bias2,
    float* __restrict__ C, int M, int N)
{
    __shared__ float As[16][132];
    __shared__ float Ws[16][132];
    int tid = threadIdx.x;
    int m0 = blockIdx.y * 128;
    int n0 = blockIdx.x * 128;
    int tx = tid & 15, ty = tid >> 4;
    int lrow = tid >> 1;
    int lk   = (tid & 1) * 8;

    float acc[8][8];
#pragma unroll
    for (int i = 0; i < 8; i++)
#pragma unroll
        for (int j = 0; j < 8; j++) acc[i][j] = 0.f;

    for (int k0 = 0; k0 < SG_K; k0 += 16) {
        {
            int gm = m0 + lrow; if (gm > M - 1) gm = M - 1;
            const float4* p = (const float4*)(A + (size_t)gm * SG_K + k0 + lk);
            float4 v0 = p[0], v1 = p[1];
            As[lk+0][lrow] = v0.x; As[lk+1][lrow] = v0.y;
            As[lk+2][lrow] = v0.z; As[lk+3][lrow] = v0.w;
            As[lk+4][lrow] = v1.x; As[lk+5][lrow] = v1.y;
            As[lk+6][lrow] = v1.z; As[lk+7][lrow] = v1.w;
            int gn = n0 + lrow; if (gn > N - 1) gn = N - 1;
            const float4* q = (const float4*)(W + (size_t)gn * SG_K + k0 + lk);
            float4 w0 = q[0], w1 = q[1];
            Ws[lk+0][lrow] = w0.x; Ws[lk+1][lrow] = w0.y;
            Ws[lk+2][lrow] = w0.z; Ws[lk+3][lrow] = w0.w;
            Ws[lk+4][lrow] = w1.x; Ws[lk+5][lrow] = w1.y;
            Ws[lk+6][lrow] = w1.z; Ws[lk+7][lrow] = w1.w;
        }
        __syncthreads();
#pragma unroll
        for (int k = 0; k < 16; k++) {
            float ra[8], rb[8];
#pragma unroll
            for (int i = 0; i < 8; i++) ra[i] = As[k][ty*8 + i];
#pragma unroll
            for (int j = 0; j < 8; j++) rb[j] = Ws[k][tx*8 + j];
#pragma unroll
            for (int i = 0; i < 8; i++)
#pragma unroll
                for (int j = 0; j < 8; j++) acc[i][j] += ra[i] * rb[j];
        }
        __syncthreads();
    }
#pragma unroll
    for (int i = 0; i < 8; i++) {
        int m = m0 + ty*8 + i;
        if (m >= M) continue;
#pragma unroll
        for (int j = 0; j < 8; j++) {
            int n = n0 + tx*8 + j;
            if (n >= N) continue;
            float v = acc[i][j];
            if (bias1)  v += bias1[n];
            if (bias2)  v += bias2[n];
            C[(size_t)m * N + n] = v;
        }
    }
}

// ---------------- 2b) fp16 m16n8k16 tensor GEMM ------------------------------
// C[M,N] = A[M,512] @ W[N,512]^T (+bias)(+addsrc). 128x128 tile, BK=32 halves
// (16 words), cp.async double buffer, PADH=20-word rows (conflict-free).
#define PADH 20

__global__ __launch_bounds__(256) void k_mm(
    const unsigned* __restrict__ A, const unsigned* __restrict__ W,
    const float* __restrict__ bias, const float* __restrict__ addsrc,
    float* __restrict__ C, int M, int N)
{
    __shared__ unsigned As[2][128 * PADH];
    __shared__ unsigned Ws[2][128 * PADH];
    int tid  = threadIdx.x;
    int lane = tid & 31, warp = tid >> 5;
    int warpM = warp & 3, warpN = warp >> 2;   // warp tile (32m, 64n)
    int m0 = blockIdx.y * 128;
    int n0 = blockIdx.x * 128;
    int lrow  = tid >> 1;          // 0..127
    int lpart = (tid & 1) * 8;     // word offset 0 or 8 (8 words = 2 x 16B)

    int gm = m0 + lrow; if (gm > M - 1) gm = M - 1;
    int gn = n0 + lrow; if (gn > N - 1) gn = N - 1;
    const unsigned* Ap = A + (size_t)gm * KW + lpart;
    const unsigned* Wp = W + (size_t)gn * KW + lpart;
    unsigned sa_base = (unsigned)__cvta_generic_to_shared(&As[0][0]);
    unsigned sw_base = (unsigned)__cvta_generic_to_shared(&Ws[0][0]);
    unsigned soff = (unsigned)(lrow * PADH + lpart) * 4u;

    float acc[2][8][4];
#pragma unroll
    for (int i = 0; i < 2; i++)
#pragma unroll
        for (int j = 0; j < 8; j++)
#pragma unroll
            for (int r = 0; r < 4; r++) acc[i][j][r] = 0.f;

    int c = lane & 3, g = lane >> 2;

#define ISSUE(s, k0w) do {                                                    \
        unsigned da = sa_base + (unsigned)(s) * 128u * PADH * 4u + soff;      \
        unsigned dw = sw_base + (unsigned)(s) * 128u * PADH * 4u + soff;      \
        const unsigned* pa = Ap + (k0w);                                      \
        const unsigned* pw = Wp + (k0w);                                      \
        asm volatile("cp.async.ca.shared.global [%0],[%1],16;\n\t"            \
                     "cp.async.ca.shared.global [%2],[%3],16;\n\t"            \
                     "cp.async.ca.shared.global [%4],[%5],16;\n\t"            \
                     "cp.async.ca.shared.global [%6],[%7],16;\n\t"            \
                     "cp.async.commit_group;\n\t"                             \
            :: "r"(da), "l"(pa), "r"(da + 16u), "l"(pa + 4),                  \
               "r"(dw), "l"(pw), "r"(dw + 16u), "l"(pw + 4));                 \
    } while (0)

    ISSUE(0, 0);
    for (int it = 0; it < 16; ++it) {
        if (it + 1 < 16) {
            ISSUE((it + 1) & 1, (it + 1) * 16);
            asm volatile("cp.async.wait_group 1;");
        } else {
            asm volatile("cp.async.wait_group 0;");
        }
        __syncthreads();
        const unsigned* as_ = &As[it & 1][0];
        const unsigned* ws_ = &Ws[it & 1][0];
        // two m16n8k16 K-steps per stage: word offsets 0 and 8
#pragma unroll
        for (int kk = 0; kk < 16; kk += 8) {
            unsigned af[2][4];
#pragma unroll
            for (int mi = 0; mi < 2; mi++) {
                int mb = warpM * 32 + mi * 16;
                af[mi][0] = as_[(mb + g    ) * PADH + kk + c    ];
                af[mi][1] = as_[(mb + g + 8) * PADH + kk + c    ];
                af[mi][2] = as_[(mb + g    ) * PADH + kk + c + 4];
                af[mi][3] = as_[(mb + g + 8) * PADH + kk + c + 4];
            }
            unsigned bf[8][2];
#pragma unroll
            for (int ni = 0; ni < 8; ni++) {
                int nb = warpN * 64 + ni * 8;
                bf[ni][0] = ws_[(nb + g) * PADH + kk + c    ];
                bf[ni][1] = ws_[(nb + g) * PADH + kk + c + 4];
            }
#pragma unroll
            for (int mi = 0; mi < 2; mi++)
#pragma unroll
                for (int ni = 0; ni < 8; ni++)
                    MMA_F16(acc[mi][ni][0], acc[mi][ni][1],
                            acc[mi][ni][2], acc[mi][ni][3],
                            af[mi][0], af[mi][1], af[mi][2], af[mi][3],
                            bf[ni][0], bf[ni][1]);
        }
        __syncthreads();
    }
#undef ISSUE
    // epilogue: c0:(g, 2q) c1:(g, 2q+1) c2:(g+8, 2q) c3:(g+8, 2q+1)
    int q = lane & 3;
#pragma unroll
    for (int mi = 0; mi < 2; mi++) {
        int m_lo = m0 + warpM * 32 + mi * 16 + g;
        int m_hi = m_lo + 8;
#pragma unroll
        for (int ni = 0; ni < 8; ni++) {
            int n = n0 + warpN * 64 + ni * 8 + 2 * q;
            if (n >= N) continue;
            float b0v = 0.f, b1v = 0.f;
            if (bias) { b0v = bias[n]; b1v = bias[n+1]; }
            if (m_lo < M) {
                float v0 = acc[mi][ni][0] + b0v;
                float v1 = acc[mi][ni][1] + b1v;
                if (addsrc) {
                    v0 += addsrc[(size_t)m_lo * N + n];
                    v1 += addsrc[(size_t)m_lo * N + n + 1];
                }
                *(float2*)(C + (size_t)m_lo * N + n) = make_float2(v0, v1);
            }
            if (m_hi < M) {
                float v2 = acc[mi][ni][2] + b0v;
                float v3 = acc[mi][ni][3] + b1v;
                if (addsrc) {
                    v2 += addsrc[(size_t)m_hi * N + n];
                    v3 += addsrc[(size_t)m_hi * N + n + 1];
                }
                *(float2*)(C + (size_t)m_hi * N + n) = make_float2(v2, v3);
            }
        }
    }
}

// ---------------- 3) transpose xg -> [t][gate_row][b] ------------------------
__global__ __launch_bounds__(256) void k_xgT()
{
    __shared__ float sm[32][33];
    int nc = blockIdx.x;
    int t  = blockIdx.y;
    int lane = threadIdx.x & 31, w = threadIdx.x >> 5;
    for (int bb = w; bb < 32; bb += 8)
        sm[lane][bb] = g_xg[(size_t)(bb * T_ + t) * G_ + nc * 32 + lane];
    __syncthreads();
    for (int nn = w; nn < 32; nn += 8)
        g_xgT[((size_t)t * G_ + nc * 32 + nn) * 32 + lane] = sm[nn][lane];
}

// ---------------- 4) persistent LSTM (R4/R6-proven barrier protocol) ---------
#define LNB 128
#define LTH 256
#define LSTM_SMEM ((16*512 + 512*32 + 16*32) * 4)

__global__ __launch_bounds__(LTH) void k_lstm(const float* __restrict__ whh)
{
    extern __shared__ float sm[];
    float* w_sm = sm;                 // [16][512]
    float* h_sm = sm + 16 * 512;      // [512][32]  h[k][b]
    float* g_sm = h_sm + 512 * 32;    // [16][32]
    int tid = threadIdx.x, bid = blockIdx.x;
    int lane = tid & 31, warp = tid >> 5;

    for (int idx = tid; idx < 16 * 512; idx += LTH) {
        int r = idx >> 9, k = idx & 511;
        int gate = r >> 2, u = r & 3;
        w_sm[idx] = whh[(size_t)(gate * H_ + bid * 4 + u) * H_ + k];
    }
    unsigned base = *((volatile unsigned*)&g_bar[bid]);
    float c_reg = 0.f;
    int uu = tid >> 5;
    __syncthreads();

    for (int t = 0; t < T_; t++) {
        if (t > 0) {
            unsigned target = base + (unsigned)t;
            for (;;) {
                int ok = 1;
                if (tid < LNB) {
                    unsigned v = *((volatile unsigned*)&g_bar[tid]);
                    ok = (v >= target) ? 1 : 0;
                }
                if (__syncthreads_and(ok)) break;
            }
            __threadfence();
            const float4* hb = (const float4*)g_hbufT[(t - 1) % 3];
            float4* hd = (float4*)h_sm;
            for (int i = tid; i < H_ * B_ / 4; i += LTH)
                hd[i] = __ldcg(hb + i);
            __syncthreads();
        }
        float a0 = 0.f, a1 = 0.f, a2 = 0.f, a3 = 0.f;
        if (t > 0 && warp < 4) {
            const float* w0 = &w_sm[(warp*4 + 0) * 512];
            const float* w1 = &w_sm[(warp*4 + 1) * 512];
            const float* w2 = &w_sm[(warp*4 + 2) * 512];
            const float* w3 = &w_sm[(warp*4 + 3) * 512];
#pragma unroll 4
            for (int k = 0; k < 512; k += 4) {
                float h0 = h_sm[(k+0)*32 + lane];
                float h1 = h_sm[(k+1)*32 + lane];
                float h2 = h_sm[(k+2)*32 + lane];
                float h3 = h_sm[(k+3)*32 + lane];
                float4 wa = *(const float4*)&w0[k];
                float4 wb = *(const float4*)&w1[k];
                float4 wc = *(const float4*)&w2[k];
                float4 wd = *(const float4*)&w3[k];
                a0 += h0*wa.x + h1*wa.y + h2*wa.z + h3*wa.w;
                a1 += h0*wb.x + h1*wb.y + h2*wb.z + h3*wb.w;
                a2 += h0*wc.x + h1*wc.y + h2*wc.z + h3*wc.w;
                a3 += h0*wd.x + h1*wd.y + h2*wd.z + h3*wd.w;
            }
        }
        if (warp < 4) {
            g_sm[(warp*4 + 0)*32 + lane] = a0;
            g_sm[(warp*4 + 1)*32 + lane] = a1;
            g_sm[(warp*4 + 2)*32 + lane] = a2;
            g_sm[(warp*4 + 3)*32 + lane] = a3;
        }
        __syncthreads();
        if (tid < 128) {
            int b = lane;
            int j = bid * 4 + uu;
            const float* xt = g_xgT + (size_t)t * G_ * B_;
            float gi = g_sm[(0*4+uu)*32 + b] + xt[((size_t)(0*H_ + j)) * B_ + b];
            float gf = g_sm[(1*4+uu)*32 + b] + xt[((size_t)(1*H_ + j)) * B_ + b];
            float gg = g_sm[(2*4+uu)*32 + b] + xt[((size_t)(2*H_ + j)) * B_ + b];
            float go = g_sm[(3*4+uu)*32 + b] + xt[((size_t)(3*H_ + j)) * B_ + b];
            float i_ = 1.f / (1.f + __expf(-gi));
            float f_ = 1.f / (1.f + __expf(-gf));
            float gv = tanhf(gg);
            float o_ = 1.f / (1.f + __expf(-go));
            c_reg = f_ * c_reg + i_ * gv;
            float h = o_ * tanhf(c_reg);
            g_hbufT[t % 3][j * B_ + b] = h;
            g_lstm[(size_t)(b * T_ + t) * H_ + j] = h;
            __threadfence();
        }
        __syncthreads();
        if (tid == 0)
            *((volatile unsigned*)&g_bar[bid]) = base + (unsigned)(t + 1);
    }
}

// ---------------- 5) attention: K^T + V staged in smem (R6-proven) -----------
#define KT_LD 264
#define VS_LD 68
#define ATT_SMEM ((64*KT_LD + 256*VS_LD + 64 + 256 + 8 + 256) * 4)

__global__ __launch_bounds__(256) void k_attn()
{
    extern __shared__ float smemf[];
    float* KT     = smemf;
    float* Vs     = KT + 64 * KT_LD;
    float* q_s    = Vs + 256 * VS_LD;
    float* attn_s = q_s + 64;
    float* red    = attn_s + 256;
    float* ctxp   = red + 8;
    int tid = threadIdx.x;
    int nh = blockIdx.x, b = blockIdx.y;
    int lane = tid & 31, w = tid >> 5;
    const float* kb = g_k + (size_t)b * S_ * H_ + nh * HD_;
    const float* vb = g_v + (size_t)b * S_ * H_ + nh * HD_;

    for (int it = 0; it < 16; ++it) {
        int idx4 = it * 256 + tid;
        int s = idx4 >> 4;
        int d4 = (idx4 & 15) * 4;
        float4 kv = *(const float4*)(kb + (size_t)s * H_ + d4);
        float4 vv = *(const float4*)(vb + (size_t)s * H_ + d4);
        KT[(d4+0)*KT_LD + s] = kv.x;
        KT[(d4+1)*KT_LD + s] = kv.y;
        KT[(d4+2)*KT_LD + s] = kv.z;
        KT[(d4+3)*KT_LD + s] = kv.w;
        *(float4*)(Vs + s * VS_LD + d4) = vv;
    }
    __syncthreads();

    for (int t = 0; t < T_; t++) {
        if (tid < 64)
            q_s[tid] = g_q[(size_t)(b * T_ + t) * H_ + nh * HD_ + tid];
        __syncthreads();
        float sc = 0.f;
#pragma unroll 16
        for (int d = 0; d < 64; d += 4) {
            sc += q_s[d+0] * KT[(d+0)*KT_LD + tid];
            sc += q_s[d+1] * KT[(d+1)*KT_LD + tid];
            sc += q_s[d+2] * KT[(d+2)*KT_LD + tid];
            sc += q_s[d+3] * KT[(d+3)*KT_LD + tid];
        }
        sc *= 0.125f;
        float mx = sc;
#pragma unroll
        for (int o = 16; o; o >>= 1) mx = fmaxf(mx, __shfl_xor_sync(0xffffffffu, mx, o));
        if (lane == 0) red[w] = mx;
        __syncthreads();
        mx = red[0];
#pragma unroll
        for (int i = 1; i < 8; i++) mx = fmaxf(mx, red[i]);
        float e = __expf(sc - mx);
        float sum = e;
#pragma unroll
        for (int o = 16; o; o >>= 1) sum += __shfl_xor_sync(0xffffffffu, sum, o);
        __syncthreads();
        if (lane == 0) red[w] = sum;
        __syncthreads();
        sum = red[0] + red[1] + red[2] + red[3] + red[4] + red[5] + red[6] + red[7];
        attn_s[tid] = e * (1.f / sum);
        __syncthreads();
        int d = tid & 63, scn = tid >> 6;
        float a = 0.f;
#pragma unroll 16
        for (int s = 0; s < 64; s++)
            a += attn_s[scn * 64 + s] * Vs[(scn * 64 + s) * VS_LD + d];
        ctxp[scn * 64 + d] = a;
        __syncthreads();
        if (tid < 64)
            g_ctx[(size_t)(b * T_ + t) * H_ + nh * HD_ + tid] =
                ctxp[0*64 + tid] + ctxp[1*64 + tid] +
                ctxp[2*64 + tid] + ctxp[3*64 + tid];
        __syncthreads();
    }
}

// ---------------- launcher ---------------------------------------------------
static inline void cvt(const float* src, unsigned* dst, size_t nelem)
{
    int n4 = (int)(nelem / 4);
    k_cvth<<<(n4 + 255) / 256, 256>>>(src, dst, n4);
}

extern "C" void kernel_launch(void* const* d_in, const int* in_sizes, int n_in,
                              void* d_out, int out_size)
{
    const int*   targets    = (const int*)  d_in[0];
    const float* enc        = (const float*)d_in[1];
    const float* embedding  = (const float*)d_in[2];
    const float* w_ih       = (const float*)d_in[3];
    const float* w_hh       = (const float*)d_in[4];
    const float* b_ih       = (const float*)d_in[5];
    const float* b_hh       = (const float*)d_in[6];
    const float* in_proj_w  = (const float*)d_in[7];
    const float* in_proj_b  = (const float*)d_in[8];
    const float* out_proj_w = (const float*)d_in[9];
    const float* out_proj_b = (const float*)d_in[10];
    const float* fc_w       = (const float*)d_in[11];
    const float* fc_b       = (const float*)d_in[12];
    float* out = (float*)d_out;

    float *p_emb, *p_xg, *p_lstm, *p_q, *p_k, *p_v, *p_ctx, *p_comb;
    unsigned *p_tA, *p_tEnc, *p_tWq, *p_tWk, *p_tWv, *p_tWo, *p_tW;
    cudaGetSymbolAddress((void**)&p_emb,  g_emb);
    cudaGetSymbolAddress((void**)&p_xg,   g_xg);
    cudaGetSymbolAddress((void**)&p_lstm, g_lstm);
    cudaGetSymbolAddress((void**)&p_q,    g_q);
    cudaGetSymbolAddress((void**)&p_k,    g_k);
    cudaGetSymbolAddress((void**)&p_v,    g_v);
    cudaGetSymbolAddress((void**)&p_ctx,  g_ctx);
    cudaGetSymbolAddress((void**)&p_comb, g_comb);
    cudaGetSymbolAddress((void**)&p_tA,   g_tA);
    cudaGetSymbolAddress((void**)&p_tEnc, g_tEnc);
    cudaGetSymbolAddress((void**)&p_tWq,  g_tWq);
    cudaGetSymbolAddress((void**)&p_tWk,  g_tWk);
    cudaGetSymbolAddress((void**)&p_tWv,  g_tWv);
    cudaGetSymbolAddress((void**)&p_tWo,  g_tWo);
    cudaGetSymbolAddress((void**)&p_tW,   g_tW);

    cudaFuncSetAttribute(k_lstm, cudaFuncAttributeMaxDynamicSharedMemorySize,
                         LSTM_SMEM);
    cudaFuncSetAttribute(k_attn, cudaFuncAttributeMaxDynamicSharedMemorySize,
                         ATT_SMEM);

    // 1) embedding gather
    k_gather<<<M_BT, 128>>>(targets, embedding);
    // 2) xg = emb @ w_ih^T + b_ih + b_hh   (fp32 FFMA: keeps recurrence exact)
    k_sgemm<<<dim3(G_/128, (M_BT+127)/128), 256>>>(p_emb, w_ih, b_ih, b_hh,
                                                   p_xg, M_BT, G_);
    // 3) transpose xg to [t][gate_row][b]
    k_xgT<<<dim3(64, T_), 256>>>();
    // 4) persistent LSTM over 127 steps
    k_lstm<<<LNB, LTH, LSTM_SMEM>>>(w_hh);
    // 5) k/v projections of encoder outputs (fp16 tensor cores)
    cvt(enc,                         p_tEnc, (size_t)M_BS * 512);
    cvt(in_proj_w + (size_t)H_*H_,   p_tWk,  (size_t)H_ * 512);
    cvt(in_proj_w + (size_t)2*H_*H_, p_tWv,  (size_t)H_ * 512);
    k_mm<<<dim3(4, M_BS/128), 256>>>(p_tEnc, p_tWk, in_proj_b + H_,
                                     nullptr, p_k, M_BS, H_);
    k_mm<<<dim3(4, M_BS/128), 256>>>(p_tEnc, p_tWv, in_proj_b + 2*H_,
                                     nullptr, p_v, M_BS, H_);
    // 6) q projection
    cvt(p_lstm,    p_tA,  (size_t)M_BT * 512);
    cvt(in_proj_w, p_tWq, (size_t)H_ * 512);
    k_mm<<<dim3(4, (M_BT+127)/128), 256>>>(p_tA, p_tWq, in_proj_b,
                                           nullptr, p_q, M_BT, H_);
    // 7) attention (smem-resident K/V)
    k_attn<<<dim3(NH_, B_), 256, ATT_SMEM>>>();
    // 8) combined = ctx @ out_proj^T + b + lstm_out (fused residual)
    cvt(p_ctx,      p_tA,  (size_t)M_BT * 512);
    cvt(out_proj_w, p_tWo, (size_t)H_ * 512);
    k_mm<<<dim3(4, (M_BT+127)/128), 256>>>(p_tA, p_tWo, out_proj_b,
                                           p_lstm, p_comb, M_BT, H_);
    // 9) logits = combined @ fc_w^T + fc_b
    cvt(p_comb, p_tA, (size_t)M_BT * 512);
    cvt(fc_w,   p_tW, (size_t)V_ * 512);
    k_mm<<<dim3((V_+127)/128, (M_BT+127)/128), 256>>>(p_tA, p_tW, fc_b,
                                                      nullptr, out, M_BT, V_);
}

// round 10
// speedup vs baseline: 1.5622x; 1.2361x over previous
#include <cuda_runtime.h>
#include <cuda_fp16.h>
#include <math.h>
#include <stdint.h>

#define B_  32
#define T_  127
#define S_  256
#define H_  512
#define V_  8000
#define NH_ 8
#define HD_ 64
#define G_  2048          // 4*H
#define M_BT (B_*T_)      // 4064
#define M_BS (B_*S_)      // 8192
#define SG_K 512
#define KW   256          // K in half2 words

// ---------------- scratch (static device globals; no allocation) -------------
__device__ float g_emb [M_BT * H_];
__device__ float g_xg  [M_BT * G_];
__device__ float g_xgTp[(size_t)T_ * B_ * G_];   // [t][b][permuted gate row]
__device__ float g_lstm[M_BT * H_];
__device__ float g_q   [M_BT * H_];
__device__ float g_k   [M_BS * H_];
__device__ float g_v   [M_BS * H_];
__device__ float g_ctx [M_BT * H_];
__device__ float g_comb[M_BT * H_];
__device__ unsigned g_whhp[(size_t)G_ * KW];     // fp16x2 permuted w_hh
__device__ unsigned g_hh  [B_ * KW];             // fp16x2 h state [b][kw]
__device__ float    g_c   [B_ * H_];             // fp32 c state [b][j]
__device__ unsigned g_tA  [(size_t)M_BT * KW];   // fp16x2 activations
__device__ unsigned g_tEnc[(size_t)M_BS * KW];   // fp16x2 encoder outputs
__device__ unsigned g_tWq [(size_t)H_ * KW];
__device__ unsigned g_tWk [(size_t)H_ * KW];
__device__ unsigned g_tWv [(size_t)H_ * KW];
__device__ unsigned g_tWo [(size_t)H_ * KW];
__device__ unsigned g_tW  [(size_t)V_ * KW];     // fp16x2 fc weights

// ---------------- fp16 mma helper --------------------------------------------
#define MMA_F16(d0,d1,d2,d3,a0,a1,a2,a3,b0,b1)                              \
    asm volatile("mma.sync.aligned.m16n8k16.row.col.f32.f16.f16.f32 "       \
                 "{%0,%1,%2,%3},{%4,%5,%6,%7},{%8,%9},{%0,%1,%2,%3};"       \
                 : "+f"(d0), "+f"(d1), "+f"(d2), "+f"(d3)                   \
                 : "r"(a0), "r"(a1), "r"(a2), "r"(a3), "r"(b0), "r"(b1))

// ---------------- 0) fp32 -> fp16x2 conversion -------------------------------
__global__ __launch_bounds__(256) void k_cvth(const float* __restrict__ in,
                                              unsigned* __restrict__ outp, int n4)
{
    int i = blockIdx.x * blockDim.x + threadIdx.x;
    if (i < n4) {
        float4 v = ((const float4*)in)[i];
        __half2 h0 = __floats2half2_rn(v.x, v.y);
        __half2 h1 = __floats2half2_rn(v.z, v.w);
        uint2 o;
        o.x = *(unsigned*)&h0;
        o.y = *(unsigned*)&h1;
        ((uint2*)outp)[i] = o;
    }
}

// ---------------- 1) embedding gather ---------------------------------------
__global__ void k_gather(const int* __restrict__ targets,
                         const float* __restrict__ emb)
{
    int m = blockIdx.x;
    int b = m / T_, t = m % T_;
    int tok = targets[b * 128 + t];
    const float4* src = (const float4*)(emb + (size_t)tok * H_);
    float4*       dst = (float4*)(g_emb + (size_t)m * H_);
    for (int i = threadIdx.x; i < H_ / 4; i += blockDim.x) dst[i] = src[i];
}

// ---------------- 2) FFMA SGEMM (xg only; error isolation) -------------------
__global__ __launch_bounds__(256) void k_sgemm(
    const float* __restrict__ A, const float* __restrict__ W,
    const float* __restrict__ bias1, const float* __restrict__ bias2,
    float* __restrict__ C, int M, int N)
{
    __shared__ float As[16][132];
    __shared__ float Ws[16][132];
    int tid = threadIdx.x;
    int m0 = blockIdx.y * 128;
    int n0 = blockIdx.x * 128;
    int tx = tid & 15, ty = tid >> 4;
    int lrow = tid >> 1;
    int lk   = (tid & 1) * 8;

    float acc[8][8];
#pragma unroll
    for (int i = 0; i < 8; i++)
#pragma unroll
        for (int j = 0; j < 8; j++) acc[i][j] = 0.f;

    for (int k0 = 0; k0 < SG_K; k0 += 16) {
        {
            int gm = m0 + lrow; if (gm > M - 1) gm = M - 1;
            const float4* p = (const float4*)(A + (size_t)gm * SG_K + k0 + lk);
            float4 v0 = p[0], v1 = p[1];
            As[lk+0][lrow] = v0.x; As[lk+1][lrow] = v0.y;
            As[lk+2][lrow] = v0.z; As[lk+3][lrow] = v0.w;
            As[lk+4][lrow] = v1.x; As[lk+5][lrow] = v1.y;
            As[lk+6][lrow] = v1.z; As[lk+7][lrow] = v1.w;
            int gn = n0 + lrow; if (gn > N - 1) gn = N - 1;
            const float4* q = (const float4*)(W + (size_t)gn * SG_K + k0 + lk);
            float4 w0 = q[0], w1 = q[1];
            Ws[lk+0][lrow] = w0.x; Ws[lk+1][lrow] = w0.y;
            Ws[lk+2][lrow] = w0.z; Ws[lk+3][lrow] = w0.w;
            Ws[lk+4][lrow] = w1.x; Ws[lk+5][lrow] = w1.y;
            Ws[lk+6][lrow] = w1.z; Ws[lk+7][lrow] = w1.w;
        }
        __syncthreads();
#pragma unroll
        for (int k = 0; k < 16; k++) {
            float ra[8], rb[8];
#pragma unroll
            for (int i = 0; i < 8; i++) ra[i] = As[k][ty*8 + i];
#pragma unroll
            for (int j = 0; j < 8; j++) rb[j] = Ws[k][tx*8 + j];
#pragma unroll
            for (int i = 0; i < 8; i++)
#pragma unroll
                for (int j = 0; j < 8; j++) acc[i][j] += ra[i] * rb[j];
        }
        __syncthreads();
    }
#pragma unroll
    for (int i = 0; i < 8; i++) {
        int m = m0 + ty*8 + i;
        if (m >= M) continue;
#pragma unroll
        for (int j = 0; j < 8; j++) {
            int n = n0 + tx*8 + j;
            if (n >= N) continue;
            float v = acc[i][j];
            if (bias1)  v += bias1[n];
            if (bias2)  v += bias2[n];
            C[(size_t)m * N + n] = v;
        }
    }
}

// ---------------- 2b) fp16 m16n8k16 tensor GEMM (R9-proven) ------------------
#define PADH 20

__global__ __launch_bounds__(256) void k_mm(
    const unsigned* __restrict__ A, const unsigned* __restrict__ W,
    const float* __restrict__ bias, const float* __restrict__ addsrc,
    float* __restrict__ C, int M, int N)
{
    __shared__ unsigned As[2][128 * PADH];
    __shared__ unsigned Ws[2][128 * PADH];
    int tid  = threadIdx.x;
    int lane = tid & 31, warp = tid >> 5;
    int warpM = warp & 3, warpN = warp >> 2;
    int m0 = blockIdx.y * 128;
    int n0 = blockIdx.x * 128;
    int lrow  = tid >> 1;
    int lpart = (tid & 1) * 8;

    int gm = m0 + lrow; if (gm > M - 1) gm = M - 1;
    int gn = n0 + lrow; if (gn > N - 1) gn = N - 1;
    const unsigned* Ap = A + (size_t)gm * KW + lpart;
    const unsigned* Wp = W + (size_t)gn * KW + lpart;
    unsigned sa_base = (unsigned)__cvta_generic_to_shared(&As[0][0]);
    unsigned sw_base = (unsigned)__cvta_generic_to_shared(&Ws[0][0]);
    unsigned soff = (unsigned)(lrow * PADH + lpart) * 4u;

    float acc[2][8][4];
#pragma unroll
    for (int i = 0; i < 2; i++)
#pragma unroll
        for (int j = 0; j < 8; j++)
#pragma unroll
            for (int r = 0; r < 4; r++) acc[i][j][r] = 0.f;

    int c = lane & 3, g = lane >> 2;

#define ISSUE(s, k0w) do {                                                    \
        unsigned da = sa_base + (unsigned)(s) * 128u * PADH * 4u + soff;      \
        unsigned dw = sw_base + (unsigned)(s) * 128u * PADH * 4u + soff;      \
        const unsigned* pa = Ap + (k0w);                                      \
        const unsigned* pw = Wp + (k0w);                                      \
        asm volatile("cp.async.ca.shared.global [%0],[%1],16;\n\t"            \
                     "cp.async.ca.shared.global [%2],[%3],16;\n\t"            \
                     "cp.async.ca.shared.global [%4],[%5],16;\n\t"            \
                     "cp.async.ca.shared.global [%6],[%7],16;\n\t"            \
                     "cp.async.commit_group;\n\t"                             \
            :: "r"(da), "l"(pa), "r"(da + 16u), "l"(pa + 4),                  \
               "r"(dw), "l"(pw), "r"(dw + 16u), "l"(pw + 4));                 \
    } while (0)

    ISSUE(0, 0);
    for (int it = 0; it < 16; ++it) {
        if (it + 1 < 16) {
            ISSUE((it + 1) & 1, (it + 1) * 16);
            asm volatile("cp.async.wait_group 1;");
        } else {
            asm volatile("cp.async.wait_group 0;");
        }
        __syncthreads();
        const unsigned* as_ = &As[it & 1][0];
        const unsigned* ws_ = &Ws[it & 1][0];
#pragma unroll
        for (int kk = 0; kk < 16; kk += 8) {
            unsigned af[2][4];
#pragma unroll
            for (int mi = 0; mi < 2; mi++) {
                int mb = warpM * 32 + mi * 16;
                af[mi][0] = as_[(mb + g    ) * PADH + kk + c    ];
                af[mi][1] = as_[(mb + g + 8) * PADH + kk + c    ];
                af[mi][2] = as_[(mb + g    ) * PADH + kk + c + 4];
                af[mi][3] = as_[(mb + g + 8) * PADH + kk + c + 4];
            }
            unsigned bf[8][2];
#pragma unroll
            for (int ni = 0; ni < 8; ni++) {
                int nb = warpN * 64 + ni * 8;
                bf[ni][0] = ws_[(nb + g) * PADH + kk + c    ];
                bf[ni][1] = ws_[(nb + g) * PADH + kk + c + 4];
            }
#pragma unroll
            for (int mi = 0; mi < 2; mi++)
#pragma unroll
                for (int ni = 0; ni < 8; ni++)
                    MMA_F16(acc[mi][ni][0], acc[mi][ni][1],
                            acc[mi][ni][2], acc[mi][ni][3],
                            af[mi][0], af[mi][1], af[mi][2], af[mi][3],
                            bf[ni][0], bf[ni][1]);
        }
        __syncthreads();
    }
#undef ISSUE
    int q = lane & 3;
#pragma unroll
    for (int mi = 0; mi < 2; mi++) {
        int m_lo = m0 + warpM * 32 + mi * 16 + g;
        int m_hi = m_lo + 8;
#pragma unroll
        for (int ni = 0; ni < 8; ni++) {
            int n = n0 + warpN * 64 + ni * 8 + 2 * q;
            if (n >= N) continue;
            float b0v = 0.f, b1v = 0.f;
            if (bias) { b0v = bias[n]; b1v = bias[n+1]; }
            if (m_lo < M) {
                float v0 = acc[mi][ni][0] + b0v;
                float v1 = acc[mi][ni][1] + b1v;
                if (addsrc) {
                    v0 += addsrc[(size_t)m_lo * N + n];
                    v1 += addsrc[(size_t)m_lo * N + n + 1];
                }
                *(float2*)(C + (size_t)m_lo * N + n) = make_float2(v0, v1);
            }
            if (m_hi < M) {
                float v2 = acc[mi][ni][2] + b0v;
                float v3 = acc[mi][ni][3] + b1v;
                if (addsrc) {
                    v2 += addsrc[(size_t)m_hi * N + n];
                    v3 += addsrc[(size_t)m_hi * N + n + 1];
                }
                *(float2*)(C + (size_t)m_hi * N + n) = make_float2(v2, v3);
            }
        }
    }
}

// ---------------- 3a) permute+convert w_hh -> fp16 [ub*128 + gate*32 + u] ----
__global__ __launch_bounds__(128) void k_permw(const float* __restrict__ whh)
{
    int prow = blockIdx.x;
    int ub = prow >> 7, r = prow & 127, gate = r >> 5, u = r & 31;
    int orow = gate * H_ + ub * 32 + u;
    const float4* src = (const float4*)(whh + (size_t)orow * H_);
    uint2* dst = (uint2*)(g_whhp + (size_t)prow * KW);
    for (int i = threadIdx.x; i < 128; i += 128) {
        float4 v = src[i];
        __half2 h0 = __floats2half2_rn(v.x, v.y);
        __half2 h1 = __floats2half2_rn(v.z, v.w);
        dst[i] = make_uint2(*(unsigned*)&h0, *(unsigned*)&h1);
    }
}

// ---------------- 3b) xg -> [t][b][permuted row] ------------------------------
__global__ __launch_bounds__(256) void k_xgTp()
{
    int t = blockIdx.x, b = blockIdx.y;
    const float* src = g_xg + ((size_t)b * T_ + t) * G_;
    float* dst = g_xgTp + ((size_t)t * B_ + b) * G_;
    for (int i = threadIdx.x; i < G_; i += 256) {
        int ub = i >> 7, r = i & 127, gate = r >> 5, u = r & 31;
        dst[i] = src[gate * H_ + ub * 32 + u];
    }
}

// ---------------- 3c) zero h/c state -----------------------------------------
__global__ void k_init()
{
    int i = blockIdx.x * 256 + threadIdx.x;
    if (i < B_ * KW) g_hh[i] = 0u;
    if (i < B_ * H_) g_c[i] = 0.f;
}

// ---------------- 4) LSTM step kernel (one graph node per timestep) ----------
// Block ub owns units [ub*32, ub*32+32): C[128,32] = Whhp[ub*128..+128] @ h^T,
// then fused gates + c/h update. fp16 operands, fp32 accum.
__global__ __launch_bounds__(256) void k_step(int t)
{
    __shared__ unsigned As2[2][128 * PADH];
    __shared__ unsigned Bs2[2][32 * PADH];
    __shared__ float CS[128 * 33];
    int tid = threadIdx.x, lane = tid & 31, w = tid >> 5;
    int ub = blockIdx.x;
    int lrow = tid >> 1, lpart = (tid & 1) * 8;

    const unsigned* Ap = g_whhp + (size_t)(ub * 128 + lrow) * KW + lpart;
    const unsigned* Bp = g_hh + (size_t)lrow * KW + lpart;   // valid tid<64
    unsigned sa = (unsigned)__cvta_generic_to_shared(&As2[0][0]);
    unsigned sb = (unsigned)__cvta_generic_to_shared(&Bs2[0][0]);
    unsigned aoff = (unsigned)(lrow * PADH + lpart) * 4u;

    float acc[4][4];
#pragma unroll
    for (int i = 0; i < 4; i++)
#pragma unroll
        for (int j = 0; j < 4; j++) acc[i][j] = 0.f;

    int c = lane & 3, g = lane >> 2;

#define SISSUE(s, k0w) do {                                                   \
        unsigned da = sa + (unsigned)(s) * 128u * PADH * 4u + aoff;           \
        const unsigned* pa = Ap + (k0w);                                      \
        asm volatile("cp.async.ca.shared.global [%0],[%1],16;\n\t"            \
                     "cp.async.ca.shared.global [%2],[%3],16;\n\t"            \
            :: "r"(da), "l"(pa), "r"(da + 16u), "l"(pa + 4));                 \
        if (tid < 64) {                                                       \
            unsigned db = sb + (unsigned)(s) * 32u * PADH * 4u + aoff;        \
            const unsigned* pb = Bp + (k0w);                                  \
            asm volatile("cp.async.ca.shared.global [%0],[%1],16;\n\t"        \
                         "cp.async.ca.shared.global [%2],[%3],16;\n\t"        \
                :: "r"(db), "l"(pb), "r"(db + 16u), "l"(pb + 4));             \
        }                                                                     \
        asm volatile("cp.async.commit_group;\n\t");                           \
    } while (0)

    SISSUE(0, 0);
    for (int it = 0; it < 16; ++it) {
        if (it + 1 < 16) {
            SISSUE((it + 1) & 1, (it + 1) * 16);
            asm volatile("cp.async.wait_group 1;");
        } else {
            asm volatile("cp.async.wait_group 0;");
        }
        __syncthreads();
        const unsigned* as_ = &As2[it & 1][0];
        const unsigned* bs_ = &Bs2[it & 1][0];
#pragma unroll
        for (int kk = 0; kk < 16; kk += 8) {
            int mb = w * 16;
            unsigned af[4];
            af[0] = as_[(mb + g    ) * PADH + kk + c    ];
            af[1] = as_[(mb + g + 8) * PADH + kk + c    ];
            af[2] = as_[(mb + g    ) * PADH + kk + c + 4];
            af[3] = as_[(mb + g + 8) * PADH + kk + c + 4];
            unsigned bf[4][2];
#pragma unroll
            for (int ni = 0; ni < 4; ni++) {
                bf[ni][0] = bs_[(ni * 8 + g) * PADH + kk + c    ];
                bf[ni][1] = bs_[(ni * 8 + g) * PADH + kk + c + 4];
            }
#pragma unroll
            for (int ni = 0; ni < 4; ni++)
                MMA_F16(acc[ni][0], acc[ni][1], acc[ni][2], acc[ni][3],
                        af[0], af[1], af[2], af[3], bf[ni][0], bf[ni][1]);
        }
        __syncthreads();
    }
#undef SISSUE
    // fragments -> CS[row*33 + batch]
    {
        int q = lane & 3;
        int r_lo = w * 16 + g, r_hi = r_lo + 8;
#pragma unroll
        for (int ni = 0; ni < 4; ni++) {
            int col = ni * 8 + 2 * q;
            CS[r_lo * 33 + col]     = acc[ni][0];
            CS[r_lo * 33 + col + 1] = acc[ni][1];
            CS[r_hi * 33 + col]     = acc[ni][2];
            CS[r_hi * 33 + col + 1] = acc[ni][3];
        }
    }
    __syncthreads();
    // gates + state update: element e = b*32 + u
    __half* hh = (__half*)g_hh;
#pragma unroll
    for (int rr = 0; rr < 4; rr++) {
        int e = tid + 256 * rr;
        int b = e >> 5, u = e & 31;
        int j = ub * 32 + u;
        const float* xgp = g_xgTp + ((size_t)t * B_ + b) * G_ + ub * 128;
        float gi = CS[(0 * 32 + u) * 33 + b] + xgp[0 * 32 + u];
        float gf = CS[(1 * 32 + u) * 33 + b] + xgp[1 * 32 + u];
        float gg = CS[(2 * 32 + u) * 33 + b] + xgp[2 * 32 + u];
        float go = CS[(3 * 32 + u) * 33 + b] + xgp[3 * 32 + u];
        float i_ = 1.f / (1.f + __expf(-gi));
        float f_ = 1.f / (1.f + __expf(-gf));
        float gv = tanhf(gg);
        float o_ = 1.f / (1.f + __expf(-go));
        float cc = f_ * g_c[b * H_ + j] + i_ * gv;
        float h  = o_ * tanhf(cc);
        g_c[b * H_ + j] = cc;
        g_lstm[((size_t)b * T_ + t) * H_ + j] = h;
        hh[(size_t)b * H_ + j] = __float2half_rn(h);
    }
}

// ---------------- 5) attention: K^T + V staged in smem (R6-proven) -----------
#define KT_LD 264
#define VS_LD 68
#define ATT_SMEM ((64*KT_LD + 256*VS_LD + 64 + 256 + 8 + 256) * 4)

__global__ __launch_bounds__(256) void k_attn()
{
    extern __shared__ float smemf[];
    float* KT     = smemf;
    float* Vs     = KT + 64 * KT_LD;
    float* q_s    = Vs + 256 * VS_LD;
    float* attn_s = q_s + 64;
    float* red    = attn_s + 256;
    float* ctxp   = red + 8;
    int tid = threadIdx.x;
    int nh = blockIdx.x, b = blockIdx.y;
    int lane = tid & 31, w = tid >> 5;
    const float* kb = g_k + (size_t)b * S_ * H_ + nh * HD_;
    const float* vb = g_v + (size_t)b * S_ * H_ + nh * HD_;

    for (int it = 0; it < 16; ++it) {
        int idx4 = it * 256 + tid;
        int s = idx4 >> 4;
        int d4 = (idx4 & 15) * 4;
        float4 kv = *(const float4*)(kb + (size_t)s * H_ + d4);
        float4 vv = *(const float4*)(vb + (size_t)s * H_ + d4);
        KT[(d4+0)*KT_LD + s] = kv.x;
        KT[(d4+1)*KT_LD + s] = kv.y;
        KT[(d4+2)*KT_LD + s] = kv.z;
        KT[(d4+3)*KT_LD + s] = kv.w;
        *(float4*)(Vs + s * VS_LD + d4) = vv;
    }
    __syncthreads();

    for (int t = 0; t < T_; t++) {
        if (tid < 64)
            q_s[tid] = g_q[(size_t)(b * T_ + t) * H_ + nh * HD_ + tid];
        __syncthreads();
        float sc = 0.f;
#pragma unroll 16
        for (int d = 0; d < 64; d += 4) {
            sc += q_s[d+0] * KT[(d+0)*KT_LD + tid];
            sc += q_s[d+1] * KT[(d+1)*KT_LD + tid];
            sc += q_s[d+2] * KT[(d+2)*KT_LD + tid];
            sc += q_s[d+3] * KT[(d+3)*KT_LD + tid];
        }
        sc *= 0.125f;
        float mx = sc;
#pragma unroll
        for (int o = 16; o; o >>= 1) mx = fmaxf(mx, __shfl_xor_sync(0xffffffffu, mx, o));
        if (lane == 0) red[w] = mx;
        __syncthreads();
        mx = red[0];
#pragma unroll
        for (int i = 1; i < 8; i++) mx = fmaxf(mx, red[i]);
        float e = __expf(sc - mx);
        float sum = e;
#pragma unroll
        for (int o = 16; o; o >>= 1) sum += __shfl_xor_sync(0xffffffffu, sum, o);
        __syncthreads();
        if (lane == 0) red[w] = sum;
        __syncthreads();
        sum = red[0] + red[1] + red[2] + red[3] + red[4] + red[5] + red[6] + red[7];
        attn_s[tid] = e * (1.f / sum);
        __syncthreads();
        int d = tid & 63, scn = tid >> 6;
        float a = 0.f;
#pragma unroll 16
        for (int s = 0; s < 64; s++)
            a += attn_s[scn * 64 + s] * Vs[(scn * 64 + s) * VS_LD + d];
        ctxp[scn * 64 + d] = a;
        __syncthreads();
        if (tid < 64)
            g_ctx[(size_t)(b * T_ + t) * H_ + nh * HD_ + tid] =
                ctxp[0*64 + tid] + ctxp[1*64 + tid] +
                ctxp[2*64 + tid] + ctxp[3*64 + tid];
        __syncthreads();
    }
}

// ---------------- launcher ---------------------------------------------------
static inline void cvt(const float* src, unsigned* dst, size_t nelem)
{
    int n4 = (int)(nelem / 4);
    k_cvth<<<(n4 + 255) / 256, 256>>>(src, dst, n4);
}

extern "C" void kernel_launch(void* const* d_in, const int* in_sizes, int n_in,
                              void* d_out, int out_size)
{
    const int*   targets    = (const int*)  d_in[0];
    const float* enc        = (const float*)d_in[1];
    const float* embedding  = (const float*)d_in[2];
    const float* w_ih       = (const float*)d_in[3];
    const float* w_hh       = (const float*)d_in[4];
    const float* b_ih       = (const float*)d_in[5];
    const float* b_hh       = (const float*)d_in[6];
    const float* in_proj_w  = (const float*)d_in[7];
    const float* in_proj_b  = (const float*)d_in[8];
    const float* out_proj_w = (const float*)d_in[9];
    const float* out_proj_b = (const float*)d_in[10];
    const float* fc_w       = (const float*)d_in[11];
    const float* fc_b       = (const float*)d_in[12];
    float* out = (float*)d_out;

    float *p_emb, *p_xg, *p_lstm, *p_q, *p_k, *p_v, *p_ctx, *p_comb;
    unsigned *p_tA, *p_tEnc, *p_tWq, *p_tWk, *p_tWv, *p_tWo, *p_tW;
    cudaGetSymbolAddress((void**)&p_emb,  g_emb);
    cudaGetSymbolAddress((void**)&p_xg,   g_xg);
    cudaGetSymbolAddress((void**)&p_lstm, g_lstm);
    cudaGetSymbolAddress((void**)&p_q,    g_q);
    cudaGetSymbolAddress((void**)&p_k,    g_k);
    cudaGetSymbolAddress((void**)&p_v,    g_v);
    cudaGetSymbolAddress((void**)&p_ctx,  g_ctx);
    cudaGetSymbolAddress((void**)&p_comb, g_comb);
    cudaGetSymbolAddress((void**)&p_tA,   g_tA);
    cudaGetSymbolAddress((void**)&p_tEnc, g_tEnc);
    cudaGetSymbolAddress((void**)&p_tWq,  g_tWq);
    cudaGetSymbolAddress((void**)&p_tWk,  g_tWk);
    cudaGetSymbolAddress((void**)&p_tWv,  g_tWv);
    cudaGetSymbolAddress((void**)&p_tWo,  g_tWo);
    cudaGetSymbolAddress((void**)&p_tW,   g_tW);

    cudaFuncSetAttribute(k_attn, cudaFuncAttributeMaxDynamicSharedMemorySize,
                         ATT_SMEM);

    // 1) embedding gather
    k_gather<<<M_BT, 128>>>(targets, embedding);
    // 2) xg = emb @ w_ih^T + b_ih + b_hh   (fp32 FFMA: keeps gates accurate)
    k_sgemm<<<dim3(G_/128, (M_BT+127)/128), 256>>>(p_emb, w_ih, b_ih, b_hh,
                                                   p_xg, M_BT, G_);
    // 3) LSTM prep: permuted fp16 w_hh, permuted xg, zero state
    k_permw<<<G_, 128>>>(w_hh);
    k_xgTp<<<dim3(T_, B_), 256>>>();
    k_init<<<64, 256>>>();
    // 4) LSTM: one graph node per timestep (stream order = recurrence order)
    for (int t = 0; t < T_; t++)
        k_step<<<16, 256>>>(t);
    // 5) k/v projections of encoder outputs (fp16 tensor cores)
    cvt(enc,                         p_tEnc, (size_t)M_BS * 512);
    cvt(in_proj_w + (size_t)H_*H_,   p_tWk,  (size_t)H_ * 512);
    cvt(in_proj_w + (size_t)2*H_*H_, p_tWv,  (size_t)H_ * 512);
    k_mm<<<dim3(4, M_BS/128), 256>>>(p_tEnc, p_tWk, in_proj_b + H_,
                                     nullptr, p_k, M_BS, H_);
    k_mm<<<dim3(4, M_BS/128), 256>>>(p_tEnc, p_tWv, in_proj_b + 2*H_,
                                     nullptr, p_v, M_BS, H_);
    // 6) q projection
    cvt(p_lstm,    p_tA,  (size_t)M_BT * 512);
    cvt(in_proj_w, p_tWq, (size_t)H_ * 512);
    k_mm<<<dim3(4, (M_BT+127)/128), 256>>>(p_tA, p_tWq, in_proj_b,
                                           nullptr, p_q, M_BT, H_);
    // 7) attention (smem-resident K/V)
    k_attn<<<dim3(NH_, B_), 256, ATT_SMEM>>>();
    // 8) combined = ctx @ out_proj^T + b + lstm_out (fused residual)
    cvt(p_ctx,      p_tA,  (size_t)M_BT * 512);
    cvt(out_proj_w, p_tWo, (size_t)H_ * 512);
    k_mm<<<dim3(4, (M_BT+127)/128), 256>>>(p_tA, p_tWo, out_proj_b,
                                           p_lstm, p_comb, M_BT, H_);
    // 9) logits = combined @ fc_w^T + fc_b
    cvt(p_comb, p_tA, (size_t)M_BT * 512);
    cvt(fc_w,   p_tW, (size_t)V_ * 512);
    k_mm<<<dim3((V_+127)/128, (M_BT+127)/128), 256>>>(p_tA, p_tW, fc_b,
                                                      nullptr, out, M_BT, V_);
}

// round 11
// speedup vs baseline: 1.5769x; 1.0095x over previous
#include <cuda_runtime.h>
#include <cuda_fp16.h>
#include <math.h>
#include <stdint.h>

#define B_  32
#define T_  127
#define S_  256
#define H_  512
#define V_  8000
#define NH_ 8
#define HD_ 64
#define G_  2048          // 4*H
#define M_BT (B_*T_)      // 4064
#define M_BS (B_*S_)      // 8192
#define KW   256          // K in half2 words

// ---------------- scratch (static device globals; no allocation) -------------
__device__ float g_xg  [M_BT * G_];
__device__ float g_xgTp[(size_t)T_ * B_ * G_];   // [t][b][permuted gate row]
__device__ float g_lstm[M_BT * H_];
__device__ float g_q   [M_BT * H_];
__device__ float g_k   [M_BS * H_];
__device__ float g_v   [M_BS * H_];
__device__ float g_ctx [M_BT * H_];
__device__ float g_comb[M_BT * H_];
__device__ unsigned g_whhp[(size_t)G_ * KW];     // fp16x2 permuted w_hh
__device__ unsigned g_hh  [B_ * KW];             // fp16x2 h state [b][kw]
__device__ float    g_c   [B_ * H_];             // fp32 c state [b][j]
__device__ unsigned g_tA  [(size_t)M_BT * KW];   // fp16x2 activations
__device__ unsigned g_tEnc[(size_t)M_BS * KW];   // fp16x2 encoder outputs
__device__ unsigned g_tWq [(size_t)H_ * KW];
__device__ unsigned g_tWk [(size_t)H_ * KW];
__device__ unsigned g_tWv [(size_t)H_ * KW];
__device__ unsigned g_tWo [(size_t)H_ * KW];
__device__ unsigned g_tW  [(size_t)V_ * KW];     // fp16x2 fc / w_ih weights

// ---------------- fp16 mma helper --------------------------------------------
#define MMA_F16(d0,d1,d2,d3,a0,a1,a2,a3,b0,b1)                              \
    asm volatile("mma.sync.aligned.m16n8k16.row.col.f32.f16.f16.f32 "       \
                 "{%0,%1,%2,%3},{%4,%5,%6,%7},{%8,%9},{%0,%1,%2,%3};"       \
                 : "+f"(d0), "+f"(d1), "+f"(d2), "+f"(d3)                   \
                 : "r"(a0), "r"(a1), "r"(a2), "r"(a3), "r"(b0), "r"(b1))

// ---------------- 0) fp32 -> fp16x2 conversion -------------------------------
__global__ __launch_bounds__(256) void k_cvth(const float* __restrict__ in,
                                              unsigned* __restrict__ outp, int n4)
{
    int i = blockIdx.x * blockDim.x + threadIdx.x;
    if (i < n4) {
        float4 v = ((const float4*)in)[i];
        __half2 h0 = __floats2half2_rn(v.x, v.y);
        __half2 h1 = __floats2half2_rn(v.z, v.w);
        uint2 o;
        o.x = *(unsigned*)&h0;
        o.y = *(unsigned*)&h1;
        ((uint2*)outp)[i] = o;
    }
}

// ---------------- 1) embedding gather -> fp16 directly -----------------------
__global__ void k_gather(const int* __restrict__ targets,
                         const float* __restrict__ emb)
{
    int m = blockIdx.x;
    int b = m / T_, t = m % T_;
    int tok = targets[b * 128 + t];
    const float4* src = (const float4*)(emb + (size_t)tok * H_);
    uint2* dst = (uint2*)(g_tA + (size_t)m * KW);
    for (int i = threadIdx.x; i < H_ / 4; i += blockDim.x) {
        float4 v = src[i];
        __half2 h0 = __floats2half2_rn(v.x, v.y);
        __half2 h1 = __floats2half2_rn(v.z, v.w);
        dst[i] = make_uint2(*(unsigned*)&h0, *(unsigned*)&h1);
    }
}

// ---------------- 2) fp16 m16n8k16 tensor GEMM (R9-proven + bias2) -----------
#define PADH 20

__global__ __launch_bounds__(256) void k_mm(
    const unsigned* __restrict__ A, const unsigned* __restrict__ W,
    const float* __restrict__ bias, const float* __restrict__ bias2,
    const float* __restrict__ addsrc,
    float* __restrict__ C, int M, int N)
{
    __shared__ unsigned As[2][128 * PADH];
    __shared__ unsigned Ws[2][128 * PADH];
    int tid  = threadIdx.x;
    int lane = tid & 31, warp = tid >> 5;
    int warpM = warp & 3, warpN = warp >> 2;
    int m0 = blockIdx.y * 128;
    int n0 = blockIdx.x * 128;
    int lrow  = tid >> 1;
    int lpart = (tid & 1) * 8;

    int gm = m0 + lrow; if (gm > M - 1) gm = M - 1;
    int gn = n0 + lrow; if (gn > N - 1) gn = N - 1;
    const unsigned* Ap = A + (size_t)gm * KW + lpart;
    const unsigned* Wp = W + (size_t)gn * KW + lpart;
    unsigned sa_base = (unsigned)__cvta_generic_to_shared(&As[0][0]);
    unsigned sw_base = (unsigned)__cvta_generic_to_shared(&Ws[0][0]);
    unsigned soff = (unsigned)(lrow * PADH + lpart) * 4u;

    float acc[2][8][4];
#pragma unroll
    for (int i = 0; i < 2; i++)
#pragma unroll
        for (int j = 0; j < 8; j++)
#pragma unroll
            for (int r = 0; r < 4; r++) acc[i][j][r] = 0.f;

    int c = lane & 3, g = lane >> 2;

#define ISSUE(s, k0w) do {                                                    \
        unsigned da = sa_base + (unsigned)(s) * 128u * PADH * 4u + soff;      \
        unsigned dw = sw_base + (unsigned)(s) * 128u * PADH * 4u + soff;      \
        const unsigned* pa = Ap + (k0w);                                      \
        const unsigned* pw = Wp + (k0w);                                      \
        asm volatile("cp.async.ca.shared.global [%0],[%1],16;\n\t"            \
                     "cp.async.ca.shared.global [%2],[%3],16;\n\t"            \
                     "cp.async.ca.shared.global [%4],[%5],16;\n\t"            \
                     "cp.async.ca.shared.global [%6],[%7],16;\n\t"            \
                     "cp.async.commit_group;\n\t"                             \
            :: "r"(da), "l"(pa), "r"(da + 16u), "l"(pa + 4),                  \
               "r"(dw), "l"(pw), "r"(dw + 16u), "l"(pw + 4));                 \
    } while (0)

    ISSUE(0, 0);
    for (int it = 0; it < 16; ++it) {
        if (it + 1 < 16) {
            ISSUE((it + 1) & 1, (it + 1) * 16);
            asm volatile("cp.async.wait_group 1;");
        } else {
            asm volatile("cp.async.wait_group 0;");
        }
        __syncthreads();
        const unsigned* as_ = &As[it & 1][0];
        const unsigned* ws_ = &Ws[it & 1][0];
#pragma unroll
        for (int kk = 0; kk < 16; kk += 8) {
            unsigned af[2][4];
#pragma unroll
            for (int mi = 0; mi < 2; mi++) {
                int mb = warpM * 32 + mi * 16;
                af[mi][0] = as_[(mb + g    ) * PADH + kk + c    ];
                af[mi][1] = as_[(mb + g + 8) * PADH + kk + c    ];
                af[mi][2] = as_[(mb + g    ) * PADH + kk + c + 4];
                af[mi][3] = as_[(mb + g + 8) * PADH + kk + c + 4];
            }
            unsigned bf[8][2];
#pragma unroll
            for (int ni = 0; ni < 8; ni++) {
                int nb = warpN * 64 + ni * 8;
                bf[ni][0] = ws_[(nb + g) * PADH + kk + c    ];
                bf[ni][1] = ws_[(nb + g) * PADH + kk + c + 4];
            }
#pragma unroll
            for (int mi = 0; mi < 2; mi++)
#pragma unroll
                for (int ni = 0; ni < 8; ni++)
                    MMA_F16(acc[mi][ni][0], acc[mi][ni][1],
                            acc[mi][ni][2], acc[mi][ni][3],
                            af[mi][0], af[mi][1], af[mi][2], af[mi][3],
                            bf[ni][0], bf[ni][1]);
        }
        __syncthreads();
    }
#undef ISSUE
    int q = lane & 3;
#pragma unroll
    for (int mi = 0; mi < 2; mi++) {
        int m_lo = m0 + warpM * 32 + mi * 16 + g;
        int m_hi = m_lo + 8;
#pragma unroll
        for (int ni = 0; ni < 8; ni++) {
            int n = n0 + warpN * 64 + ni * 8 + 2 * q;
            if (n >= N) continue;
            float b0v = 0.f, b1v = 0.f;
            if (bias)  { b0v += bias[n];  b1v += bias[n+1]; }
            if (bias2) { b0v += bias2[n]; b1v += bias2[n+1]; }
            if (m_lo < M) {
                float v0 = acc[mi][ni][0] + b0v;
                float v1 = acc[mi][ni][1] + b1v;
                if (addsrc) {
                    v0 += addsrc[(size_t)m_lo * N + n];
                    v1 += addsrc[(size_t)m_lo * N + n + 1];
                }
                *(float2*)(C + (size_t)m_lo * N + n) = make_float2(v0, v1);
            }
            if (m_hi < M) {
                float v2 = acc[mi][ni][2] + b0v;
                float v3 = acc[mi][ni][3] + b1v;
                if (addsrc) {
                    v2 += addsrc[(size_t)m_hi * N + n];
                    v3 += addsrc[(size_t)m_hi * N + n + 1];
                }
                *(float2*)(C + (size_t)m_hi * N + n) = make_float2(v2, v3);
            }
        }
    }
}

// ---------------- 3a) permute+convert w_hh -> fp16 [ub*128 + gate*32 + u] ----
__global__ __launch_bounds__(128) void k_permw(const float* __restrict__ whh)
{
    int prow = blockIdx.x;
    int ub = prow >> 7, r = prow & 127, gate = r >> 5, u = r & 31;
    int orow = gate * H_ + ub * 32 + u;
    const float4* src = (const float4*)(whh + (size_t)orow * H_);
    uint2* dst = (uint2*)(g_whhp + (size_t)prow * KW);
    for (int i = threadIdx.x; i < 128; i += 128) {
        float4 v = src[i];
        __half2 h0 = __floats2half2_rn(v.x, v.y);
        __half2 h1 = __floats2half2_rn(v.z, v.w);
        dst[i] = make_uint2(*(unsigned*)&h0, *(unsigned*)&h1);
    }
}

// ---------------- 3b) xg -> [t][b][permuted row] ------------------------------
__global__ __launch_bounds__(256) void k_xgTp()
{
    int t = blockIdx.x, b = blockIdx.y;
    const float* src = g_xg + ((size_t)b * T_ + t) * G_;
    float* dst = g_xgTp + ((size_t)t * B_ + b) * G_;
    for (int i = threadIdx.x; i < G_; i += 256) {
        int ub = i >> 7, r = i & 127, gate = r >> 5, u = r & 31;
        dst[i] = src[gate * H_ + ub * 32 + u];
    }
}

// ---------------- 3c) zero h/c state -----------------------------------------
__global__ void k_init()
{
    int i = blockIdx.x * 256 + threadIdx.x;
    if (i < B_ * KW) g_hh[i] = 0u;
    if (i < B_ * H_) g_c[i] = 0.f;
}

// ---------------- 4) LSTM step kernel v2 (deep pipeline + B preload) ---------
// Block ub: C[128,32] = Whhp[ub*128..+128] @ h^T, fused gate update.
// B (h, 32KB) preloaded once; A pipelined 3-deep over 16 K-stages.
#define AST  4
#define LDB  260
#define SMEM_STEP ((AST*128*PADH + 32*LDB + 128*33) * 4)

__global__ __launch_bounds__(256) void k_step(int t)
{
    extern __shared__ unsigned smw[];
    unsigned* As4 = smw;                       // [AST][128*PADH]
    unsigned* BsF = smw + AST * 128 * PADH;    // [32][LDB]
    float*    CS  = (float*)(BsF + 32 * LDB);  // [128][33]
    int tid = threadIdx.x, lane = tid & 31, w = tid >> 5;
    int ub = blockIdx.x;
    int lrow = tid >> 1, lpart = (tid & 1) * 8;

    const unsigned* Ap = g_whhp + (size_t)(ub * 128 + lrow) * KW + lpart;
    unsigned sa = (unsigned)__cvta_generic_to_shared(As4);
    unsigned aoff = (unsigned)(lrow * PADH + lpart) * 4u;

#define AISSUE(s) do {                                                        \
        unsigned da = sa + (unsigned)((s) & 3) * 128u * PADH * 4u + aoff;     \
        const unsigned* pa = Ap + (s) * 16;                                   \
        asm volatile("cp.async.ca.shared.global [%0],[%1],16;\n\t"            \
                     "cp.async.ca.shared.global [%2],[%3],16;\n\t"            \
                     "cp.async.commit_group;\n\t"                             \
            :: "r"(da), "l"(pa), "r"(da + 16u), "l"(pa + 4));                 \
    } while (0)

    // A prologue: 3 stages in flight
    AISSUE(0); AISSUE(1); AISSUE(2);

    // B preload: h[32][256] -> BsF, 8 uint4 per thread
    {
        int r = tid >> 3, c0 = (tid & 7) * 32;
        const uint4* pb = (const uint4*)(g_hh + (size_t)r * KW + c0);
        uint4* db = (uint4*)(BsF + r * LDB + c0);
#pragma unroll
        for (int i = 0; i < 8; i++) db[i] = pb[i];
    }

    float acc[4][4];
#pragma unroll
    for (int i = 0; i < 4; i++)
#pragma unroll
        for (int j = 0; j < 4; j++) acc[i][j] = 0.f;

    int c = lane & 3, g = lane >> 2;

#pragma unroll 1
    for (int s = 0; s < 16; ++s) {
        if (s + 3 < 16) {
            AISSUE(s + 3);
            asm volatile("cp.async.wait_group 3;");
        } else if (s == 13) asm volatile("cp.async.wait_group 2;");
        else if (s == 14)   asm volatile("cp.async.wait_group 1;");
        else                asm volatile("cp.async.wait_group 0;");
        __syncthreads();
        const unsigned* as_ = As4 + (s & 3) * 128 * PADH;
        int kbase = s * 16;
#pragma unroll
        for (int kk = 0; kk < 16; kk += 8) {
            int mb = w * 16;
            unsigned af[4];
            af[0] = as_[(mb + g    ) * PADH + kk + c    ];
            af[1] = as_[(mb + g + 8) * PADH + kk + c    ];
            af[2] = as_[(mb + g    ) * PADH + kk + c + 4];
            af[3] = as_[(mb + g + 8) * PADH + kk + c + 4];
            unsigned bf[4][2];
#pragma unroll
            for (int ni = 0; ni < 4; ni++) {
                bf[ni][0] = BsF[(ni * 8 + g) * LDB + kbase + kk + c    ];
                bf[ni][1] = BsF[(ni * 8 + g) * LDB + kbase + kk + c + 4];
            }
#pragma unroll
            for (int ni = 0; ni < 4; ni++)
                MMA_F16(acc[ni][0], acc[ni][1], acc[ni][2], acc[ni][3],
                        af[0], af[1], af[2], af[3], bf[ni][0], bf[ni][1]);
        }
        __syncthreads();
    }
#undef AISSUE
    // fragments -> CS[row*33 + batch]
    {
        int q = lane & 3;
        int r_lo = w * 16 + g, r_hi = r_lo + 8;
#pragma unroll
        for (int ni = 0; ni < 4; ni++) {
            int col = ni * 8 + 2 * q;
            CS[r_lo * 33 + col]     = acc[ni][0];
            CS[r_lo * 33 + col + 1] = acc[ni][1];
            CS[r_hi * 33 + col]     = acc[ni][2];
            CS[r_hi * 33 + col + 1] = acc[ni][3];
        }
    }
    __syncthreads();
    // gates + state update: element e = b*32 + u
    __half* hh = (__half*)g_hh;
    __half* ta = (__half*)g_tA;
#pragma unroll
    for (int rr = 0; rr < 4; rr++) {
        int e = tid + 256 * rr;
        int b = e >> 5, u = e & 31;
        int j = ub * 32 + u;
        const float* xgp = g_xgTp + ((size_t)t * B_ + b) * G_ + ub * 128;
        float gi = CS[(0 * 32 + u) * 33 + b] + xgp[0 * 32 + u];
        float gf = CS[(1 * 32 + u) * 33 + b] + xgp[1 * 32 + u];
        float gg = CS[(2 * 32 + u) * 33 + b] + xgp[2 * 32 + u];
        float go = CS[(3 * 32 + u) * 33 + b] + xgp[3 * 32 + u];
        float i_ = 1.f / (1.f + __expf(-gi));
        float f_ = 1.f / (1.f + __expf(-gf));
        float gv = tanhf(gg);
        float o_ = 1.f / (1.f + __expf(-go));
        float cc = f_ * g_c[b * H_ + j] + i_ * gv;
        float h  = o_ * tanhf(cc);
        g_c[b * H_ + j] = cc;
        g_lstm[((size_t)b * T_ + t) * H_ + j] = h;
        __half hf = __float2half_rn(h);
        hh[(size_t)b * H_ + j] = hf;
        ta[((size_t)b * T_ + t) * H_ + j] = hf;   // fp16 activations for q proj
    }
}

// ---------------- 5) attention: K^T + V staged in smem (R6-proven) -----------
#define KT_LD 264
#define VS_LD 68
#define ATT_SMEM ((64*KT_LD + 256*VS_LD + 64 + 256 + 8 + 256) * 4)

__global__ __launch_bounds__(256) void k_attn()
{
    extern __shared__ float smemf[];
    float* KT     = smemf;
    float* Vs     = KT + 64 * KT_LD;
    float* q_s    = Vs + 256 * VS_LD;
    float* attn_s = q_s + 64;
    float* red    = attn_s + 256;
    float* ctxp   = red + 8;
    int tid = threadIdx.x;
    int nh = blockIdx.x, b = blockIdx.y;
    int lane = tid & 31, w = tid >> 5;
    const float* kb = g_k + (size_t)b * S_ * H_ + nh * HD_;
    const float* vb = g_v + (size_t)b * S_ * H_ + nh * HD_;

    for (int it = 0; it < 16; ++it) {
        int idx4 = it * 256 + tid;
        int s = idx4 >> 4;
        int d4 = (idx4 & 15) * 4;
        float4 kv = *(const float4*)(kb + (size_t)s * H_ + d4);
        float4 vv = *(const float4*)(vb + (size_t)s * H_ + d4);
        KT[(d4+0)*KT_LD + s] = kv.x;
        KT[(d4+1)*KT_LD + s] = kv.y;
        KT[(d4+2)*KT_LD + s] = kv.z;
        KT[(d4+3)*KT_LD + s] = kv.w;
        *(float4*)(Vs + s * VS_LD + d4) = vv;
    }
    __syncthreads();

    for (int t = 0; t < T_; t++) {
        if (tid < 64)
            q_s[tid] = g_q[(size_t)(b * T_ + t) * H_ + nh * HD_ + tid];
        __syncthreads();
        float sc = 0.f;
#pragma unroll 16
        for (int d = 0; d < 64; d += 4) {
            sc += q_s[d+0] * KT[(d+0)*KT_LD + tid];
            sc += q_s[d+1] * KT[(d+1)*KT_LD + tid];
            sc += q_s[d+2] * KT[(d+2)*KT_LD + tid];
            sc += q_s[d+3] * KT[(d+3)*KT_LD + tid];
        }
        sc *= 0.125f;
        float mx = sc;
#pragma unroll
        for (int o = 16; o; o >>= 1) mx = fmaxf(mx, __shfl_xor_sync(0xffffffffu, mx, o));
        if (lane == 0) red[w] = mx;
        __syncthreads();
        mx = red[0];
#pragma unroll
        for (int i = 1; i < 8; i++) mx = fmaxf(mx, red[i]);
        float e = __expf(sc - mx);
        float sum = e;
#pragma unroll
        for (int o = 16; o; o >>= 1) sum += __shfl_xor_sync(0xffffffffu, sum, o);
        __syncthreads();
        if (lane == 0) red[w] = sum;
        __syncthreads();
        sum = red[0] + red[1] + red[2] + red[3] + red[4] + red[5] + red[6] + red[7];
        attn_s[tid] = e * (1.f / sum);
        __syncthreads();
        int d = tid & 63, scn = tid >> 6;
        float a = 0.f;
#pragma unroll 16
        for (int s = 0; s < 64; s++)
            a += attn_s[scn * 64 + s] * Vs[(scn * 64 + s) * VS_LD + d];
        ctxp[scn * 64 + d] = a;
        __syncthreads();
        if (tid < 64)
            g_ctx[(size_t)(b * T_ + t) * H_ + nh * HD_ + tid] =
                ctxp[0*64 + tid] + ctxp[1*64 + tid] +
                ctxp[2*64 + tid] + ctxp[3*64 + tid];
        __syncthreads();
    }
}

// ---------------- launcher ---------------------------------------------------
static inline void cvt(const float* src, unsigned* dst, size_t nelem)
{
    int n4 = (int)(nelem / 4);
    k_cvth<<<(n4 + 255) / 256, 256>>>(src, dst, n4);
}

extern "C" void kernel_launch(void* const* d_in, const int* in_sizes, int n_in,
                              void* d_out, int out_size)
{
    const int*   targets    = (const int*)  d_in[0];
    const float* enc        = (const float*)d_in[1];
    const float* embedding  = (const float*)d_in[2];
    const float* w_ih       = (const float*)d_in[3];
    const float* w_hh       = (const float*)d_in[4];
    const float* b_ih       = (const float*)d_in[5];
    const float* b_hh       = (const float*)d_in[6];
    const float* in_proj_w  = (const float*)d_in[7];
    const float* in_proj_b  = (const float*)d_in[8];
    const float* out_proj_w = (const float*)d_in[9];
    const float* out_proj_b = (const float*)d_in[10];
    const float* fc_w       = (const float*)d_in[11];
    const float* fc_b       = (const float*)d_in[12];
    float* out = (float*)d_out;

    float *p_xg, *p_lstm, *p_q, *p_k, *p_v, *p_ctx, *p_comb;
    unsigned *p_tA, *p_tEnc, *p_tWq, *p_tWk, *p_tWv, *p_tWo, *p_tW;
    cudaGetSymbolAddress((void**)&p_xg,   g_xg);
    cudaGetSymbolAddress((void**)&p_lstm, g_lstm);
    cudaGetSymbolAddress((void**)&p_q,    g_q);
    cudaGetSymbolAddress((void**)&p_k,    g_k);
    cudaGetSymbolAddress((void**)&p_v,    g_v);
    cudaGetSymbolAddress((void**)&p_ctx,  g_ctx);
    cudaGetSymbolAddress((void**)&p_comb, g_comb);
    cudaGetSymbolAddress((void**)&p_tA,   g_tA);
    cudaGetSymbolAddress((void**)&p_tEnc, g_tEnc);
    cudaGetSymbolAddress((void**)&p_tWq,  g_tWq);
    cudaGetSymbolAddress((void**)&p_tWk,  g_tWk);
    cudaGetSymbolAddress((void**)&p_tWv,  g_tWv);
    cudaGetSymbolAddress((void**)&p_tWo,  g_tWo);
    cudaGetSymbolAddress((void**)&p_tW,   g_tW);

    cudaFuncSetAttribute(k_attn, cudaFuncAttributeMaxDynamicSharedMemorySize,
                         ATT_SMEM);
    cudaFuncSetAttribute(k_step, cudaFuncAttributeMaxDynamicSharedMemorySize,
                         SMEM_STEP);

    // 1) embedding gather (fp16 output)
    k_gather<<<M_BT, 128>>>(targets, embedding);
    // 2) xg = emb @ w_ih^T + b_ih + b_hh   (fp16 tensor cores; g_tW reused)
    cvt(w_ih, p_tW, (size_t)G_ * 512);
    k_mm<<<dim3(G_/128, (M_BT+127)/128), 256>>>(p_tA, p_tW, b_ih, b_hh,
                                                nullptr, p_xg, M_BT, G_);
    // 3) LSTM prep: permuted fp16 w_hh, permuted xg, zero state
    k_permw<<<G_, 128>>>(w_hh);
    k_xgTp<<<dim3(T_, B_), 256>>>();
    k_init<<<64, 256>>>();
    // 4) LSTM: one graph node per timestep
    for (int t = 0; t < T_; t++)
        k_step<<<16, 256, SMEM_STEP>>>(t);
    // 5) k/v projections of encoder outputs
    cvt(enc,                         p_tEnc, (size_t)M_BS * 512);
    cvt(in_proj_w + (size_t)H_*H_,   p_tWk,  (size_t)H_ * 512);
    cvt(in_proj_w + (size_t)2*H_*H_, p_tWv,  (size_t)H_ * 512);
    k_mm<<<dim3(4, M_BS/128), 256>>>(p_tEnc, p_tWk, in_proj_b + H_, nullptr,
                                     nullptr, p_k, M_BS, H_);
    k_mm<<<dim3(4, M_BS/128), 256>>>(p_tEnc, p_tWv, in_proj_b + 2*H_, nullptr,
                                     nullptr, p_v, M_BS, H_);
    // 6) q projection (p_tA holds fp16 h written by k_step)
    cvt(in_proj_w, p_tWq, (size_t)H_ * 512);
    k_mm<<<dim3(4, (M_BT+127)/128), 256>>>(p_tA, p_tWq, in_proj_b, nullptr,
                                           nullptr, p_q, M_BT, H_);
    // 7) attention (smem-resident K/V)
    k_attn<<<dim3(NH_, B_), 256, ATT_SMEM>>>();
    // 8) combined = ctx @ out_proj^T + b + lstm_out (fused residual)
    cvt(p_ctx,      p_tA,  (size_t)M_BT * 512);
    cvt(out_proj_w, p_tWo, (size_t)H_ * 512);
    k_mm<<<dim3(4, (M_BT+127)/128), 256>>>(p_tA, p_tWo, out_proj_b, nullptr,
                                           p_lstm, p_comb, M_BT, H_);
    // 9) logits = combined @ fc_w^T + fc_b
    cvt(p_comb, p_tA, (size_t)M_BT * 512);
    cvt(fc_w,   p_tW, (size_t)V_ * 512);
    k_mm<<<dim3((V_+127)/128, (M_BT+127)/128), 256>>>(p_tA, p_tW, fc_b,
                                                      nullptr, nullptr,
                                                      out, M_BT, V_);
}